// round 2
// baseline (speedup 1.0000x reference)
#include <cuda_runtime.h>
#include <cstdint>

// ---------------------------------------------------------------------------
// Problem constants
// ---------------------------------------------------------------------------
#define B_   32
#define SQ_  2048
#define SKV_ 2048
#define D_   128

#define QT   64      // q rows per block
#define KT   32      // kv rows per tile
#define NW   8       // warps per block
#define RPW  8       // q rows per warp
#define KS4  33      // float4 stride of K/V smem tiles (conflict-free padding)

#define DROP_KEEP 0.7f
#define INV_KEEP  (1.0f / 0.7f)

// JAX key(42) -> uint32 key words (0, 42)
#define TKEY0 0u
#define TKEY1 42u

// Mask scheme:
//   2 = partitionable, bits = out0 ^ out1  (JAX >= 0.5 path for bit_width 32)
//   1 = partitionable, bits = out1 (low word)  -- tried R1, FAILED (0.77)
//   0 = legacy split-iota
#define MASK_MODE 2

// ---------------------------------------------------------------------------
// Threefry-2x32 (20 rounds) exactly as in jax/_src/prng.py
// ---------------------------------------------------------------------------
__device__ __forceinline__ uint32_t rotl32(uint32_t x, int d) {
    return __funnelshift_l(x, x, d);
}

__device__ __forceinline__ void tf_round(uint32_t& x0, uint32_t& x1, int r) {
    x0 += x1;
    x1 = rotl32(x1, r) ^ x0;
}

__device__ __forceinline__ void threefry2x32(uint32_t& x0, uint32_t& x1) {
    const uint32_t ks0 = TKEY0;
    const uint32_t ks1 = TKEY1;
    const uint32_t ks2 = 0x1BD11BDAu ^ TKEY0 ^ TKEY1;
    x0 += ks0; x1 += ks1;
    tf_round(x0, x1, 13); tf_round(x0, x1, 15); tf_round(x0, x1, 26); tf_round(x0, x1, 6);
    x0 += ks1; x1 += ks2 + 1u;
    tf_round(x0, x1, 17); tf_round(x0, x1, 29); tf_round(x0, x1, 16); tf_round(x0, x1, 24);
    x0 += ks2; x1 += ks0 + 2u;
    tf_round(x0, x1, 13); tf_round(x0, x1, 15); tf_round(x0, x1, 26); tf_round(x0, x1, 6);
    x0 += ks0; x1 += ks1 + 3u;
    tf_round(x0, x1, 17); tf_round(x0, x1, 29); tf_round(x0, x1, 16); tf_round(x0, x1, 24);
    x0 += ks1; x1 += ks2 + 4u;
    tf_round(x0, x1, 13); tf_round(x0, x1, 15); tf_round(x0, x1, 26); tf_round(x0, x1, 6);
    x0 += ks2; x1 += ks0 + 5u;
}

// uniform [0,1) for flat element index i of the (B,Sq,Skv) mask
__device__ __forceinline__ float jax_uniform(uint32_t idx) {
#if MASK_MODE == 2
    // partitionable: counts = iota(u64); (out0,out1) = threefry(key, (hi, lo));
    // for bit_width 32: bits = out0 ^ out1. idx < 2^27 so hi = 0.
    uint32_t x0 = 0u, x1 = idx;
    threefry2x32(x0, x1);
    uint32_t bits = x0 ^ x1;
#elif MASK_MODE == 1
    uint32_t x0 = 0u, x1 = idx;
    threefry2x32(x0, x1);
    uint32_t bits = x1;
#else
    // legacy: counts = iota(2^27) split in halves; pair j = (j, j+half)
    const uint32_t half = (uint32_t)(B_) * SQ_ * SKV_ / 2u;  // 2^26
    uint32_t x0, x1;
    bool first = idx < half;
    if (first) { x0 = idx;        x1 = idx + half; }
    else       { x0 = idx - half; x1 = idx;        }
    threefry2x32(x0, x1);
    uint32_t bits = first ? x0 : x1;
#endif
    return __uint_as_float((bits >> 9) | 0x3f800000u) - 1.0f;
}

// ---------------------------------------------------------------------------
// Fused flash-attention + deterministic dropout, fp32 SIMT
// ---------------------------------------------------------------------------
__global__ void __launch_bounds__(256, 2)
attn_dropout_kernel(const float* __restrict__ q,
                    const float* __restrict__ k,
                    const float* __restrict__ v,
                    const float* __restrict__ sf,
                    float* __restrict__ out) {
    const int b    = blockIdx.y;
    const int q0   = blockIdx.x * QT;
    const int tid  = threadIdx.x;
    const int w    = tid >> 5;
    const int lane = tid & 31;

    extern __shared__ float smem[];
    float4* Qs4 = (float4*)smem;                     // QT * 32 float4
    float4* Ks4 = Qs4 + QT * (D_ / 4);               // KT * KS4 float4
    float4* Vs4 = Ks4 + KT * KS4;                    // KT * KS4 float4
    float*  Ps  = (float*)(Vs4 + KT * KS4) + w * (RPW * KT);

    const float scale = sf[b];

    // Load Q tile, folding in the per-batch score scale
    const float4* qg = (const float4*)(q + ((long)b * SQ_ + q0) * D_);
    for (int f = tid; f < QT * (D_ / 4); f += blockDim.x) {
        float4 t = qg[f];
        t.x *= scale; t.y *= scale; t.z *= scale; t.w *= scale;
        Qs4[f] = t;
    }

    float  m[RPW], l[RPW];
    float4 o[RPW];
#pragma unroll
    for (int r = 0; r < RPW; r++) {
        m[r] = -3.402823466e38f;
        l[r] = 0.0f;
        o[r] = make_float4(0.f, 0.f, 0.f, 0.f);
    }

    const float4* kg = (const float4*)(k + (long)b * SKV_ * D_);
    const float4* vg = (const float4*)(v + (long)b * SKV_ * D_);

    const uint32_t row_base = (uint32_t)(b * SQ_ + q0 + w * RPW);

    for (int kt = 0; kt < SKV_ / KT; kt++) {
        __syncthreads();
        // Stage K, V tiles (coalesced global, padded smem)
        for (int f = tid; f < KT * (D_ / 4); f += blockDim.x) {
            int ki = f >> 5, d4 = f & 31;
            Ks4[ki * KS4 + d4] = kg[(kt * KT + ki) * (D_ / 4) + d4];
            Vs4[ki * KS4 + d4] = vg[(kt * KT + ki) * (D_ / 4) + d4];
        }
        __syncthreads();

        // ---- QK^T : lane = ki, full D dot per lane ----
        float s[RPW];
#pragma unroll
        for (int r = 0; r < RPW; r++) s[r] = 0.0f;

        const float4* kp = Ks4 + lane * KS4;
        const float4* qp = Qs4 + (w * RPW) * (D_ / 4);
#pragma unroll 8
        for (int d4 = 0; d4 < D_ / 4; d4++) {
            float4 kv = kp[d4];
#pragma unroll
            for (int r = 0; r < RPW; r++) {
                float4 qv = qp[r * (D_ / 4) + d4];
                s[r] = fmaf(qv.x, kv.x,
                       fmaf(qv.y, kv.y,
                       fmaf(qv.z, kv.z,
                       fmaf(qv.w, kv.w, s[r]))));
            }
        }

        // ---- online softmax + dropout, stage P through smem ----
        float alpha[RPW];
#pragma unroll
        for (int r = 0; r < RPW; r++) {
            float t = s[r];
#pragma unroll
            for (int off = 16; off; off >>= 1)
                t = fmaxf(t, __shfl_xor_sync(0xffffffffu, t, off));
            float mnew = fmaxf(m[r], t);
            alpha[r] = __expf(m[r] - mnew);
            float p = __expf(s[r] - mnew);
            float ps = p;
#pragma unroll
            for (int off = 16; off; off >>= 1)
                ps += __shfl_xor_sync(0xffffffffu, ps, off);
            l[r] = l[r] * alpha[r] + ps;   // denominator includes dropped terms
            m[r] = mnew;

            // dropout mask: flat index into (B, Sq, Skv), fits in u32 (2^27)
            uint32_t idx = (row_base + (uint32_t)r) * (uint32_t)SKV_
                         + (uint32_t)(kt * KT + lane);
            float u = jax_uniform(idx);
            Ps[r * KT + lane] = (u < DROP_KEEP) ? p * INV_KEEP : 0.0f;
        }
        __syncwarp();

        // ---- P @ V : lane = d-chunk (float4) ----
#pragma unroll
        for (int r = 0; r < RPW; r++) {
            float a = alpha[r];
            o[r].x *= a; o[r].y *= a; o[r].z *= a; o[r].w *= a;
        }
#pragma unroll 4
        for (int ki = 0; ki < KT; ki++) {
            float4 v4 = Vs4[ki * KS4 + lane];
#pragma unroll
            for (int r = 0; r < RPW; r++) {
                float p = Ps[r * KT + ki];
                o[r].x = fmaf(p, v4.x, o[r].x);
                o[r].y = fmaf(p, v4.y, o[r].y);
                o[r].z = fmaf(p, v4.z, o[r].z);
                o[r].w = fmaf(p, v4.w, o[r].w);
            }
        }
        __syncwarp();
    }

    // ---- epilogue: divide by softmax denominator, store ----
    float4* og = (float4*)(out + ((long)b * SQ_ + q0 + w * RPW) * D_);
#pragma unroll
    for (int r = 0; r < RPW; r++) {
        float inv = 1.0f / l[r];
        float4 t = o[r];
        t.x *= inv; t.y *= inv; t.z *= inv; t.w *= inv;
        og[r * (D_ / 4) + lane] = t;
    }
}

// ---------------------------------------------------------------------------
// Launch
// ---------------------------------------------------------------------------
extern "C" void kernel_launch(void* const* d_in, const int* in_sizes, int n_in,
                              void* d_out, int out_size) {
    const float* q  = (const float*)d_in[0];
    const float* k  = (const float*)d_in[1];
    const float* v  = (const float*)d_in[2];
    const float* sf = (const float*)d_in[3];
    float* out = (float*)d_out;

    const int smem_bytes =
        (QT * (D_ / 4) + 2 * KT * KS4) * 16 + NW * RPW * KT * 4;  // 74752

    cudaFuncSetAttribute(attn_dropout_kernel,
                         cudaFuncAttributeMaxDynamicSharedMemorySize, smem_bytes);

    dim3 grid(SQ_ / QT, B_);
    attn_dropout_kernel<<<grid, 256, smem_bytes>>>(q, k, v, sf, out);
}

// round 7
// speedup vs baseline: 1.0784x; 1.0784x over previous
#include <cuda_runtime.h>
#include <cuda_bf16.h>
#include <mma.h>
#include <cstdint>

using namespace nvcuda;

#define B_    32
#define SQ_   2048
#define SKV_  2048
#define D_    128
#define MT    64       // q rows per CTA
#define NT    64       // kv rows per tile
#define NTILES (SKV_/NT)
#define NTHREADS 256

#define DROP_KEEP 0.7f
#define INV_KEEP  (1.0f/0.7f)
#define LOG2E_F   1.4426950408889634f

// smem element strides (in elements)
#define SKQ 136   // bf16, Q/K/V tiles ([rows][128] padded)
#define SPP 72    // bf16, P tiles ([64][64] padded)
#define SSS 72    // fp32, S tile
#define SOO 132   // fp32, O tile

// smem byte offsets
enum {
  OFF_QH = 0,       OFF_QM = 17408,  OFF_QL = 34816,   // 64*136*2 each
  OFF_KH = 52224,   OFF_KM = 69632,  OFF_KL = 87040,
  OFF_VH = 104448,  OFF_VL = 121856,
  OFF_PH = 139264,  OFF_PL = 148480,                   // 64*72*2 each
  OFF_S  = 157696,                                     // 64*72*4
  OFF_O  = 176128,                                     // 64*132*4
  SMEM_TOTAL = 209920
};

// ---------------------------------------------------------------------------
// JAX threefry2x32, key=(0,42); bits = x0 ^ x1 (partitionable — validated R2)
// ---------------------------------------------------------------------------
__device__ __forceinline__ uint32_t rotl32(uint32_t x, int d) { return __funnelshift_l(x, x, d); }
__device__ __forceinline__ void tf_round(uint32_t& x0, uint32_t& x1, int r) {
    x0 += x1; x1 = rotl32(x1, r) ^ x0;
}
__device__ __forceinline__ uint32_t tf_bits(uint32_t idx) {
    const uint32_t ks0 = 0u, ks1 = 42u, ks2 = 0x1BD11BDAu ^ 42u;
    uint32_t x0 = 0u, x1 = idx;
    x0 += ks0; x1 += ks1;
    tf_round(x0, x1, 13); tf_round(x0, x1, 15); tf_round(x0, x1, 26); tf_round(x0, x1, 6);
    x0 += ks1; x1 += ks2 + 1u;
    tf_round(x0, x1, 17); tf_round(x0, x1, 29); tf_round(x0, x1, 16); tf_round(x0, x1, 24);
    x0 += ks2; x1 += ks0 + 2u;
    tf_round(x0, x1, 13); tf_round(x0, x1, 15); tf_round(x0, x1, 26); tf_round(x0, x1, 6);
    x0 += ks0; x1 += ks1 + 3u;
    tf_round(x0, x1, 17); tf_round(x0, x1, 29); tf_round(x0, x1, 16); tf_round(x0, x1, 24);
    x0 += ks1; x1 += ks2 + 4u;
    tf_round(x0, x1, 13); tf_round(x0, x1, 15); tf_round(x0, x1, 26); tf_round(x0, x1, 6);
    x0 += ks2; x1 += ks0 + 5u;
    return x0 ^ x1;
}

__device__ __forceinline__ uint32_t pack2(__nv_bfloat16 a, __nv_bfloat16 b) {
    return (uint32_t)__bfloat16_as_ushort(a) | ((uint32_t)__bfloat16_as_ushort(b) << 16);
}

// 3-way bf16 split of a float
__device__ __forceinline__ void split3(float x, __nv_bfloat16& h, __nv_bfloat16& m,
                                       __nv_bfloat16& l) {
    h = __float2bfloat16(x);
    float rm = x - __bfloat162float(h);
    m = __float2bfloat16(rm);
    l = __float2bfloat16(rm - __bfloat162float(m));
}
__device__ __forceinline__ void split2(float x, __nv_bfloat16& h, __nv_bfloat16& l) {
    h = __float2bfloat16(x);
    l = __float2bfloat16(x - __bfloat162float(h));
}

typedef wmma::fragment<wmma::matrix_a, 16, 16, 16, __nv_bfloat16, wmma::row_major> FragA;
typedef wmma::fragment<wmma::matrix_b, 16, 16, 16, __nv_bfloat16, wmma::col_major> FragBK;
typedef wmma::fragment<wmma::matrix_b, 16, 16, 16, __nv_bfloat16, wmma::row_major> FragBV;
typedef wmma::fragment<wmma::accumulator, 16, 16, 16, float> FragC;

__global__ void __launch_bounds__(NTHREADS, 1)
attn_wmma_kernel(const float* __restrict__ q,
                 const float* __restrict__ k,
                 const float* __restrict__ v,
                 const float* __restrict__ sf,
                 float* __restrict__ out) {
    extern __shared__ char smem[];
    __nv_bfloat16* QH = (__nv_bfloat16*)(smem + OFF_QH);
    __nv_bfloat16* QM = (__nv_bfloat16*)(smem + OFF_QM);
    __nv_bfloat16* QL = (__nv_bfloat16*)(smem + OFF_QL);
    __nv_bfloat16* KH = (__nv_bfloat16*)(smem + OFF_KH);
    __nv_bfloat16* KM = (__nv_bfloat16*)(smem + OFF_KM);
    __nv_bfloat16* KL = (__nv_bfloat16*)(smem + OFF_KL);
    __nv_bfloat16* VH = (__nv_bfloat16*)(smem + OFF_VH);
    __nv_bfloat16* VL = (__nv_bfloat16*)(smem + OFF_VL);
    __nv_bfloat16* PH = (__nv_bfloat16*)(smem + OFF_PH);
    __nv_bfloat16* PL = (__nv_bfloat16*)(smem + OFF_PL);
    float* Sf = (float*)(smem + OFF_S);
    float* Of = (float*)(smem + OFF_O);

    const int b   = blockIdx.y;
    const int q0  = blockIdx.x * MT;
    const int tid = threadIdx.x;
    const int w   = tid >> 5;
    const int r   = tid >> 2;     // my q row (0..63), 4 threads per row
    const int seg = tid & 3;      // 16-col segment within the kv tile

    // zero O accumulator (includes padding; harmless)
    for (int f = tid; f < MT * SOO; f += NTHREADS) Of[f] = 0.0f;

    // ---- stage Q (scale folded), 3-way split ----
    {
        const float scale = sf[b];
        const float4* qg4 = (const float4*)(q + ((long)(b * SQ_ + q0)) * D_);
        for (int f = tid; f < MT * D_ / 4; f += NTHREADS) {
            int rr = f >> 5, c = (f & 31) * 4;
            float4 x = qg4[f];
            float xs[4] = {x.x * scale, x.y * scale, x.z * scale, x.w * scale};
            __nv_bfloat16 h[4], m[4], l[4];
#pragma unroll
            for (int j = 0; j < 4; j++) split3(xs[j], h[j], m[j], l[j]);
            uint32_t idx = rr * SKQ + c;
            *(uint2*)(QH + idx) = make_uint2(pack2(h[0], h[1]), pack2(h[2], h[3]));
            *(uint2*)(QM + idx) = make_uint2(pack2(m[0], m[1]), pack2(m[2], m[3]));
            *(uint2*)(QL + idx) = make_uint2(pack2(l[0], l[1]), pack2(l[2], l[3]));
        }
    }

    float mrow = -3.402823466e38f, lrow = 0.0f;
    const uint32_t rowg = (uint32_t)(b * SQ_ + q0 + r);
    const float4* kg4 = (const float4*)(k + (long)b * SKV_ * D_);
    const float4* vg4 = (const float4*)(v + (long)b * SKV_ * D_);

    for (int t = 0; t < NTILES; t++) {
        const int kv0 = t * NT;

        // ---- stage K (3-split) and V (2-split), row-major [64][128] ----
        for (int f = tid; f < NT * D_ / 4; f += NTHREADS) {
            int rr = f >> 5, c = (f & 31) * 4;
            uint32_t idx = rr * SKQ + c;
            float4 kx = kg4[(kv0 * D_ / 4) + f];
            __nv_bfloat16 h[4], m[4], l[4];
            split3(kx.x, h[0], m[0], l[0]); split3(kx.y, h[1], m[1], l[1]);
            split3(kx.z, h[2], m[2], l[2]); split3(kx.w, h[3], m[3], l[3]);
            *(uint2*)(KH + idx) = make_uint2(pack2(h[0], h[1]), pack2(h[2], h[3]));
            *(uint2*)(KM + idx) = make_uint2(pack2(m[0], m[1]), pack2(m[2], m[3]));
            *(uint2*)(KL + idx) = make_uint2(pack2(l[0], l[1]), pack2(l[2], l[3]));

            float4 vx = vg4[(kv0 * D_ / 4) + f];
            __nv_bfloat16 vh[4], vl[4];
            split2(vx.x, vh[0], vl[0]); split2(vx.y, vh[1], vl[1]);
            split2(vx.z, vh[2], vl[2]); split2(vx.w, vh[3], vl[3]);
            *(uint2*)(VH + idx) = make_uint2(pack2(vh[0], vh[1]), pack2(vh[2], vh[3]));
            *(uint2*)(VL + idx) = make_uint2(pack2(vl[0], vl[1]), pack2(vl[2], vl[3]));
        }
        __syncthreads();

        // ---- QK: S[64][64] = Q·K^T, 6 split-product passes fused per k-step ----
        {
            const int m0 = (w & 3) * 16;
            const int n0 = (w >> 2) * 2;       // subtile col base (units of 16)
            FragC acc[2];
            wmma::fill_fragment(acc[0], 0.0f);
            wmma::fill_fragment(acc[1], 0.0f);
            for (int kk = 0; kk < D_; kk += 16) {
                FragA aH, aM, aL;
                wmma::load_matrix_sync(aH, QH + m0 * SKQ + kk, SKQ);
                wmma::load_matrix_sync(aM, QM + m0 * SKQ + kk, SKQ);
                wmma::load_matrix_sync(aL, QL + m0 * SKQ + kk, SKQ);
#pragma unroll
                for (int nn = 0; nn < 2; nn++) {
                    const int nc = (n0 + nn) * 16;
                    FragBK bH, bM, bL;
                    wmma::load_matrix_sync(bH, KH + nc * SKQ + kk, SKQ);
                    wmma::load_matrix_sync(bM, KM + nc * SKQ + kk, SKQ);
                    wmma::load_matrix_sync(bL, KL + nc * SKQ + kk, SKQ);
                    wmma::mma_sync(acc[nn], aH, bH, acc[nn]);
                    wmma::mma_sync(acc[nn], aH, bM, acc[nn]);
                    wmma::mma_sync(acc[nn], aM, bH, acc[nn]);
                    wmma::mma_sync(acc[nn], aH, bL, acc[nn]);
                    wmma::mma_sync(acc[nn], aL, bH, acc[nn]);
                    wmma::mma_sync(acc[nn], aM, bM, acc[nn]);
                }
            }
            wmma::store_matrix_sync(Sf + m0 * SSS + n0 * 16, acc[0], SSS, wmma::mem_row_major);
            wmma::store_matrix_sync(Sf + m0 * SSS + (n0 + 1) * 16, acc[1], SSS, wmma::mem_row_major);
        }
        __syncthreads();

        // ---- epilogue: softmax + dropout; P splits; rescale O ----
        {
            const float* Srow = Sf + r * SSS + seg * 16;
            float4 s4a = *(const float4*)(Srow + 0);
            float4 s4b = *(const float4*)(Srow + 4);
            float4 s4c = *(const float4*)(Srow + 8);
            float4 s4d = *(const float4*)(Srow + 12);
            float sv[16] = {s4a.x, s4a.y, s4a.z, s4a.w, s4b.x, s4b.y, s4b.z, s4b.w,
                            s4c.x, s4c.y, s4c.z, s4c.w, s4d.x, s4d.y, s4d.z, s4d.w};
            float lm = sv[0];
#pragma unroll
            for (int j = 1; j < 16; j++) lm = fmaxf(lm, sv[j]);
            lm = fmaxf(lm, __shfl_xor_sync(0xffffffffu, lm, 1));
            lm = fmaxf(lm, __shfl_xor_sync(0xffffffffu, lm, 2));
            float mnew  = fmaxf(mrow, lm);
            float alpha = exp2f((mrow - mnew) * LOG2E_F);

            float lp = 0.0f;
            const uint32_t idx0 = rowg * (uint32_t)SKV_ + (uint32_t)(kv0 + seg * 16);
            const int pbase = r * SPP + seg * 16;
#pragma unroll
            for (int j = 0; j < 16; j += 2) {
                float p0 = exp2f((sv[j] - mnew) * LOG2E_F);
                float p1 = exp2f((sv[j + 1] - mnew) * LOG2E_F);
                lp += p0 + p1;
                uint32_t b0 = tf_bits(idx0 + (uint32_t)j);
                uint32_t b1 = tf_bits(idx0 + (uint32_t)j + 1u);
                float u0 = __uint_as_float((b0 >> 9) | 0x3f800000u) - 1.0f;
                float u1 = __uint_as_float((b1 >> 9) | 0x3f800000u) - 1.0f;
                float pd0 = (u0 < DROP_KEEP) ? p0 * INV_KEEP : 0.0f;
                float pd1 = (u1 < DROP_KEEP) ? p1 * INV_KEEP : 0.0f;
                __nv_bfloat16 h0, l0, h1, l1;
                split2(pd0, h0, l0); split2(pd1, h1, l1);
                *(uint32_t*)(PH + pbase + j) = pack2(h0, h1);
                *(uint32_t*)(PL + pbase + j) = pack2(l0, l1);
            }
            lp += __shfl_xor_sync(0xffffffffu, lp, 1);
            lp += __shfl_xor_sync(0xffffffffu, lp, 2);
            lrow = lrow * alpha + lp;
            mrow = mnew;

            if (t > 0 && alpha != 1.0f) {
                float4* op = (float4*)(Of + r * SOO + seg * 32);
#pragma unroll
                for (int j = 0; j < 8; j++) {
                    float4 o4 = op[j];
                    o4.x *= alpha; o4.y *= alpha; o4.z *= alpha; o4.w *= alpha;
                    op[j] = o4;
                }
            }
        }
        __syncthreads();

        // ---- PV: O[64][128] += P·V, 3 split-product passes fused per k-step ----
        {
            const int m0 = (w & 3) * 16;
            const int n0 = (w >> 2) * 4;      // subtile col base (units of 16)
            FragC acc[4];
#pragma unroll
            for (int i = 0; i < 4; i++)
                wmma::load_matrix_sync(acc[i], Of + m0 * SOO + (n0 + i) * 16, SOO,
                                       wmma::mem_row_major);
            for (int kk = 0; kk < NT; kk += 16) {
                FragA pHf, pLf;
                wmma::load_matrix_sync(pHf, PH + m0 * SPP + kk, SPP);
                wmma::load_matrix_sync(pLf, PL + m0 * SPP + kk, SPP);
#pragma unroll
                for (int i = 0; i < 4; i++) {
                    FragBV vHf, vLf;
                    wmma::load_matrix_sync(vHf, VH + kk * SKQ + (n0 + i) * 16, SKQ);
                    wmma::load_matrix_sync(vLf, VL + kk * SKQ + (n0 + i) * 16, SKQ);
                    wmma::mma_sync(acc[i], pHf, vHf, acc[i]);
                    wmma::mma_sync(acc[i], pHf, vLf, acc[i]);
                    wmma::mma_sync(acc[i], pLf, vHf, acc[i]);
                }
            }
#pragma unroll
            for (int i = 0; i < 4; i++)
                wmma::store_matrix_sync(Of + m0 * SOO + (n0 + i) * 16, acc[i], SOO,
                                        wmma::mem_row_major);
        }
        __syncthreads();
    }

    // ---- final: O / l -> gmem ----
    {
        float inv = 1.0f / lrow;
        const float* orow = Of + r * SOO + seg * 32;
        float4* og = (float4*)(out + ((long)(b * SQ_ + q0 + r)) * D_ + seg * 32);
#pragma unroll
        for (int j = 0; j < 8; j++) {
            float4 o4 = *(const float4*)(orow + j * 4);
            o4.x *= inv; o4.y *= inv; o4.z *= inv; o4.w *= inv;
            og[j] = o4;
        }
    }
}

// ---------------------------------------------------------------------------
extern "C" void kernel_launch(void* const* d_in, const int* in_sizes, int n_in,
                              void* d_out, int out_size) {
    const float* q  = (const float*)d_in[0];
    const float* k  = (const float*)d_in[1];
    const float* v  = (const float*)d_in[2];
    const float* sf = (const float*)d_in[3];
    float* out = (float*)d_out;

    cudaFuncSetAttribute(attn_wmma_kernel,
                         cudaFuncAttributeMaxDynamicSharedMemorySize, SMEM_TOTAL);

    dim3 grid(SQ_ / MT, B_);
    attn_wmma_kernel<<<grid, NTHREADS, SMEM_TOTAL>>>(q, k, v, sf, out);
}

// round 8
// speedup vs baseline: 1.3370x; 1.2398x over previous
#include <cuda_runtime.h>
#include <cuda_bf16.h>
#include <cstdint>

#define B_    32
#define SQ_   2048
#define SKV_  2048
#define D_    128
#define MT    128      // q rows per CTA (8 warps x 16 rows)
#define NT    64       // kv rows per tile
#define NTILES (SKV_/NT)
#define NTHREADS 256

#define DROP_KEEP 0.7f
#define INV_KEEP  (1.0f/0.7f)
#define LOG2E_F   1.4426950408889634f

#define SKQ 136   // element stride, Q/K tiles  (banks 4g+tig -> conflict-free)
#define SVT 72    // element stride, V^T tile   (banks 4g+tig -> conflict-free)

// smem byte offsets
enum {
  OFF_QH = 0,      OFF_QM = 34816,  OFF_QL = 69632,    // 128*136*2 each
  OFF_KH = 104448, OFF_KM = 121856, OFF_KL = 139264,   // 64*136*2 each
  OFF_VTH = 156672, OFF_VTL = 175104,                  // 128*72*2 each
  SMEM_TOTAL = 193536
};

// ---------------------------------------------------------------------------
// JAX threefry2x32, key=(0,42); bits = x0 ^ x1 (validated R2)
// ---------------------------------------------------------------------------
__device__ __forceinline__ uint32_t rotl32(uint32_t x, int d) { return __funnelshift_l(x, x, d); }
__device__ __forceinline__ void tf_round(uint32_t& x0, uint32_t& x1, int r) {
    x0 += x1; x1 = rotl32(x1, r) ^ x0;
}
__device__ __forceinline__ uint32_t tf_bits(uint32_t idx) {
    const uint32_t ks0 = 0u, ks1 = 42u, ks2 = 0x1BD11BDAu ^ 42u;
    uint32_t x0 = 0u, x1 = idx;
    x0 += ks0; x1 += ks1;
    tf_round(x0, x1, 13); tf_round(x0, x1, 15); tf_round(x0, x1, 26); tf_round(x0, x1, 6);
    x0 += ks1; x1 += ks2 + 1u;
    tf_round(x0, x1, 17); tf_round(x0, x1, 29); tf_round(x0, x1, 16); tf_round(x0, x1, 24);
    x0 += ks2; x1 += ks0 + 2u;
    tf_round(x0, x1, 13); tf_round(x0, x1, 15); tf_round(x0, x1, 26); tf_round(x0, x1, 6);
    x0 += ks0; x1 += ks1 + 3u;
    tf_round(x0, x1, 17); tf_round(x0, x1, 29); tf_round(x0, x1, 16); tf_round(x0, x1, 24);
    x0 += ks1; x1 += ks2 + 4u;
    tf_round(x0, x1, 13); tf_round(x0, x1, 15); tf_round(x0, x1, 26); tf_round(x0, x1, 6);
    x0 += ks2; x1 += ks0 + 5u;
    return x0 ^ x1;
}

__device__ __forceinline__ uint32_t pack2(__nv_bfloat16 a, __nv_bfloat16 b) {
    return (uint32_t)__bfloat16_as_ushort(a) | ((uint32_t)__bfloat16_as_ushort(b) << 16);
}
// pack two floats -> bf16x2 (lo = first elem)
__device__ __forceinline__ uint32_t packf2(float lo, float hi) {
    uint32_t d;
    asm("cvt.rn.bf16x2.f32 %0, %1, %2;" : "=r"(d) : "f"(hi), "f"(lo));
    return d;
}
__device__ __forceinline__ void split3(float x, __nv_bfloat16& h, __nv_bfloat16& m,
                                       __nv_bfloat16& l) {
    h = __float2bfloat16(x);
    float rm = x - __bfloat162float(h);
    m = __float2bfloat16(rm);
    l = __float2bfloat16(rm - __bfloat162float(m));
}
__device__ __forceinline__ void split2(float x, __nv_bfloat16& h, __nv_bfloat16& l) {
    h = __float2bfloat16(x);
    l = __float2bfloat16(x - __bfloat162float(h));
}

// mma.sync m16n8k16 row.col f32.bf16.bf16.f32, D==C accumulate in place
__device__ __forceinline__ void mma16816(float c[4], const uint32_t a[4], const uint32_t b[2]) {
    asm volatile("mma.sync.aligned.m16n8k16.row.col.f32.bf16.bf16.f32 "
        "{%0,%1,%2,%3}, {%4,%5,%6,%7}, {%8,%9}, {%0,%1,%2,%3};"
        : "+f"(c[0]), "+f"(c[1]), "+f"(c[2]), "+f"(c[3])
        : "r"(a[0]), "r"(a[1]), "r"(a[2]), "r"(a[3]), "r"(b[0]), "r"(b[1]));
}

__device__ __forceinline__ void lda4(uint32_t a[4], const __nv_bfloat16* p, int tig) {
    a[0] = *(const uint32_t*)(p + 2 * tig);
    a[1] = *(const uint32_t*)(p + 8 * SKQ + 2 * tig);
    a[2] = *(const uint32_t*)(p + 2 * tig + 8);
    a[3] = *(const uint32_t*)(p + 8 * SKQ + 2 * tig + 8);
}
__device__ __forceinline__ void ldb2(uint32_t b[2], const __nv_bfloat16* p, int tig) {
    b[0] = *(const uint32_t*)(p + 2 * tig);
    b[1] = *(const uint32_t*)(p + 2 * tig + 8);
}

__global__ void __launch_bounds__(NTHREADS, 1)
attn_fa2_kernel(const float* __restrict__ q,
                const float* __restrict__ k,
                const float* __restrict__ v,
                const float* __restrict__ sf,
                float* __restrict__ out) {
    extern __shared__ char smem[];
    __nv_bfloat16* QH  = (__nv_bfloat16*)(smem + OFF_QH);
    __nv_bfloat16* QM  = (__nv_bfloat16*)(smem + OFF_QM);
    __nv_bfloat16* QL  = (__nv_bfloat16*)(smem + OFF_QL);
    __nv_bfloat16* KH  = (__nv_bfloat16*)(smem + OFF_KH);
    __nv_bfloat16* KM  = (__nv_bfloat16*)(smem + OFF_KM);
    __nv_bfloat16* KL  = (__nv_bfloat16*)(smem + OFF_KL);
    __nv_bfloat16* VTH = (__nv_bfloat16*)(smem + OFF_VTH);
    __nv_bfloat16* VTL = (__nv_bfloat16*)(smem + OFF_VTL);

    const int b    = blockIdx.y;
    const int q0   = blockIdx.x * MT;
    const int tid  = threadIdx.x;
    const int w    = tid >> 5;
    const int lane = tid & 31;
    const int g    = lane >> 2;     // group row
    const int tig  = lane & 3;      // thread in group
    const int m0   = w * 16;        // warp's q-row base within tile

    // ---- stage Q (scale folded), 3-way split ----
    {
        const float scale = sf[b];
        const float4* qg4 = (const float4*)(q + ((long)(b * SQ_ + q0)) * D_);
        for (int f = tid; f < MT * D_ / 4; f += NTHREADS) {
            int rr = f >> 5, c = (f & 31) * 4;
            float4 x = qg4[f];
            float xs[4] = {x.x * scale, x.y * scale, x.z * scale, x.w * scale};
            __nv_bfloat16 h[4], m[4], l[4];
#pragma unroll
            for (int j = 0; j < 4; j++) split3(xs[j], h[j], m[j], l[j]);
            uint32_t idx = rr * SKQ + c;
            *(uint2*)(QH + idx) = make_uint2(pack2(h[0], h[1]), pack2(h[2], h[3]));
            *(uint2*)(QM + idx) = make_uint2(pack2(m[0], m[1]), pack2(m[2], m[3]));
            *(uint2*)(QL + idx) = make_uint2(pack2(l[0], l[1]), pack2(l[2], l[3]));
        }
    }

    // O accumulators: 16 n-tiles (128 d cols), 4 floats each
    float O[16][4];
#pragma unroll
    for (int nt = 0; nt < 16; nt++) { O[nt][0] = O[nt][1] = O[nt][2] = O[nt][3] = 0.0f; }
    float mr0 = -3.402823466e38f, mr1 = -3.402823466e38f, lr0 = 0.0f, lr1 = 0.0f;

    const float4* kg4 = (const float4*)(k + (long)b * SKV_ * D_);
    const float*  vg  = v + (long)b * SKV_ * D_;
    const uint32_t rowbase = (uint32_t)(b * SQ_ + q0 + m0);

    for (int t = 0; t < NTILES; t++) {
        const int kv0 = t * NT;
        __syncthreads();   // previous tile's MMAs done reading K/VT

        // ---- stage K (3-split), row-major [64][SKQ] ----
        for (int f = tid; f < NT * D_ / 4; f += NTHREADS) {
            int rr = f >> 5, c = (f & 31) * 4;
            float4 kx = kg4[(kv0 * D_ / 4) + f];
            __nv_bfloat16 h[4], m[4], l[4];
            split3(kx.x, h[0], m[0], l[0]); split3(kx.y, h[1], m[1], l[1]);
            split3(kx.z, h[2], m[2], l[2]); split3(kx.w, h[3], m[3], l[3]);
            uint32_t idx = rr * SKQ + c;
            *(uint2*)(KH + idx) = make_uint2(pack2(h[0], h[1]), pack2(h[2], h[3]));
            *(uint2*)(KM + idx) = make_uint2(pack2(m[0], m[1]), pack2(m[2], m[3]));
            *(uint2*)(KL + idx) = make_uint2(pack2(l[0], l[1]), pack2(l[2], l[3]));
        }
        // ---- stage V transposed (2-split): VT[d][kv], pairs of kv rows ----
        for (int f = tid; f < D_ * (NT / 2); f += NTHREADS) {
            int c = f & 127;         // d col
            int rr = (f >> 7) * 2;   // kv row pair
            float v0 = vg[(kv0 + rr) * D_ + c];
            float v1 = vg[(kv0 + rr + 1) * D_ + c];
            __nv_bfloat16 h0, l0, h1, l1;
            split2(v0, h0, l0); split2(v1, h1, l1);
            *(uint32_t*)(VTH + c * SVT + rr) = pack2(h0, h1);
            *(uint32_t*)(VTL + c * SVT + rr) = pack2(l0, l1);
        }
        __syncthreads();

        // ---- QK: S[16][64] in regs, 6 split passes ----
        float sacc[8][4];
#pragma unroll
        for (int nt = 0; nt < 8; nt++) { sacc[nt][0] = sacc[nt][1] = sacc[nt][2] = sacc[nt][3] = 0.0f; }

        for (int k8 = 0; k8 < 8; k8++) {
            const int kk = k8 * 16;
            uint32_t aH[4], aM[4], aL[4];
            const int qoff = (m0 + g) * SKQ + kk;
            lda4(aH, QH + qoff, tig);
            lda4(aM, QM + qoff, tig);
            lda4(aL, QL + qoff, tig);
#pragma unroll
            for (int nt = 0; nt < 8; nt++) {
                const int kr = (8 * nt + g) * SKQ + kk;
                uint32_t bH[2], bM[2], bL[2];
                ldb2(bH, KH + kr, tig);
                ldb2(bM, KM + kr, tig);
                ldb2(bL, KL + kr, tig);
                mma16816(sacc[nt], aH, bH);
                mma16816(sacc[nt], aH, bM);
                mma16816(sacc[nt], aM, bH);
                mma16816(sacc[nt], aH, bL);
                mma16816(sacc[nt], aL, bH);
                mma16816(sacc[nt], aM, bM);
            }
        }

        // ---- softmax + dropout, all intra-warp ----
        float mx0 = sacc[0][0], mx1 = sacc[0][2];
#pragma unroll
        for (int nt = 0; nt < 8; nt++) {
            mx0 = fmaxf(mx0, fmaxf(sacc[nt][0], sacc[nt][1]));
            mx1 = fmaxf(mx1, fmaxf(sacc[nt][2], sacc[nt][3]));
        }
        mx0 = fmaxf(mx0, __shfl_xor_sync(0xffffffffu, mx0, 1));
        mx0 = fmaxf(mx0, __shfl_xor_sync(0xffffffffu, mx0, 2));
        mx1 = fmaxf(mx1, __shfl_xor_sync(0xffffffffu, mx1, 1));
        mx1 = fmaxf(mx1, __shfl_xor_sync(0xffffffffu, mx1, 2));
        float mn0 = fmaxf(mr0, mx0), mn1 = fmaxf(mr1, mx1);
        float al0 = exp2f((mr0 - mn0) * LOG2E_F);
        float al1 = exp2f((mr1 - mn1) * LOG2E_F);

        uint32_t pHa[8], pHb[8], pLa[8], pLb[8];
        float ls0 = 0.0f, ls1 = 0.0f;
        const uint32_t idx00 = (rowbase + (uint32_t)g) * (uint32_t)SKV_
                             + (uint32_t)(kv0 + 2 * tig);
#pragma unroll
        for (int nt = 0; nt < 8; nt++) {
            float p0 = exp2f((sacc[nt][0] - mn0) * LOG2E_F);
            float p1 = exp2f((sacc[nt][1] - mn0) * LOG2E_F);
            float p2 = exp2f((sacc[nt][2] - mn1) * LOG2E_F);
            float p3 = exp2f((sacc[nt][3] - mn1) * LOG2E_F);
            ls0 += p0 + p1; ls1 += p2 + p3;
            uint32_t ia = idx00 + (uint32_t)(8 * nt);
            uint32_t ib = ia + 8u * (uint32_t)SKV_;
            float u0 = __uint_as_float((tf_bits(ia)      >> 9) | 0x3f800000u) - 1.0f;
            float u1 = __uint_as_float((tf_bits(ia + 1u) >> 9) | 0x3f800000u) - 1.0f;
            float u2 = __uint_as_float((tf_bits(ib)      >> 9) | 0x3f800000u) - 1.0f;
            float u3 = __uint_as_float((tf_bits(ib + 1u) >> 9) | 0x3f800000u) - 1.0f;
            float d0 = (u0 < DROP_KEEP) ? p0 * INV_KEEP : 0.0f;
            float d1 = (u1 < DROP_KEEP) ? p1 * INV_KEEP : 0.0f;
            float d2 = (u2 < DROP_KEEP) ? p2 * INV_KEEP : 0.0f;
            float d3 = (u3 < DROP_KEEP) ? p3 * INV_KEEP : 0.0f;
            pHa[nt] = packf2(d0, d1);
            pHb[nt] = packf2(d2, d3);
            float r0 = d0 - __bfloat162float(__float2bfloat16(d0));
            float r1 = d1 - __bfloat162float(__float2bfloat16(d1));
            float r2 = d2 - __bfloat162float(__float2bfloat16(d2));
            float r3 = d3 - __bfloat162float(__float2bfloat16(d3));
            pLa[nt] = packf2(r0, r1);
            pLb[nt] = packf2(r2, r3);
        }
        ls0 += __shfl_xor_sync(0xffffffffu, ls0, 1);
        ls0 += __shfl_xor_sync(0xffffffffu, ls0, 2);
        ls1 += __shfl_xor_sync(0xffffffffu, ls1, 1);
        ls1 += __shfl_xor_sync(0xffffffffu, ls1, 2);
        lr0 = lr0 * al0 + ls0;
        lr1 = lr1 * al1 + ls1;
        mr0 = mn0; mr1 = mn1;

        // ---- rescale O in registers ----
#pragma unroll
        for (int nt = 0; nt < 16; nt++) {
            O[nt][0] *= al0; O[nt][1] *= al0;
            O[nt][2] *= al1; O[nt][3] *= al1;
        }

        // ---- PV: O += P * V (P from registers, V^T from smem) ----
#pragma unroll
        for (int kkp = 0; kkp < 4; kkp++) {
            uint32_t aH[4] = { pHa[2 * kkp], pHb[2 * kkp], pHa[2 * kkp + 1], pHb[2 * kkp + 1] };
            uint32_t aL[4] = { pLa[2 * kkp], pLb[2 * kkp], pLa[2 * kkp + 1], pLb[2 * kkp + 1] };
#pragma unroll
            for (int nt = 0; nt < 16; nt++) {
                const int vr = (8 * nt + g) * SVT + 16 * kkp;
                uint32_t bH[2], bL[2];
                ldb2(bH, VTH + vr, tig);
                ldb2(bL, VTL + vr, tig);
                mma16816(O[nt], aH, bH);
                mma16816(O[nt], aH, bL);
                mma16816(O[nt], aL, bH);
            }
        }
    }

    // ---- final: O / l -> gmem ----
    {
        float inv0 = 1.0f / lr0, inv1 = 1.0f / lr1;
        long row0 = (long)(b * SQ_ + q0 + m0 + g);
        float* o0 = out + row0 * D_ + 2 * tig;
        float* o1 = out + (row0 + 8) * D_ + 2 * tig;
#pragma unroll
        for (int nt = 0; nt < 16; nt++) {
            *(float2*)(o0 + 8 * nt) = make_float2(O[nt][0] * inv0, O[nt][1] * inv0);
            *(float2*)(o1 + 8 * nt) = make_float2(O[nt][2] * inv1, O[nt][3] * inv1);
        }
    }
}

// ---------------------------------------------------------------------------
extern "C" void kernel_launch(void* const* d_in, const int* in_sizes, int n_in,
                              void* d_out, int out_size) {
    const float* q  = (const float*)d_in[0];
    const float* k  = (const float*)d_in[1];
    const float* v  = (const float*)d_in[2];
    const float* sf = (const float*)d_in[3];
    float* out = (float*)d_out;

    cudaFuncSetAttribute(attn_fa2_kernel,
                         cudaFuncAttributeMaxDynamicSharedMemorySize, SMEM_TOTAL);

    dim3 grid(SQ_ / MT, B_);
    attn_fa2_kernel<<<grid, NTHREADS, SMEM_TOTAL>>>(q, k, v, sf, out);
}

// round 9
// speedup vs baseline: 1.8884x; 1.4124x over previous
#include <cuda_runtime.h>
#include <cuda_bf16.h>
#include <cstdint>

#define B_    32
#define SQ_   2048
#define SKV_  2048
#define D_    128
#define MT    128
#define NT    64
#define NTILES (SKV_/NT)
#define NTHREADS 256

#define INV_KEEP  (1.0f/0.7f)
#define LOG2E_F   1.4426950408889634f
// keep <=> tf_bits < KEEP_THRESH  (exact integer form of u < 0.7f)
#define KEEP_THRESH 0xB3333400u

#define SKQ 136           // element stride (272 B) -> 4-bank row step, LDSM conflict-free
#define ROWB (SKQ*2)      // 272

enum {
  OFF_QH = 0,      OFF_QM = 34816,  OFF_QL = 69632,    // 128*272
  OFF_KH = 104448, OFF_KM = 121856, OFF_KL = 139264,   // 64*272
  OFF_VH = 156672, OFF_VL = 174080,
  SMEM_TOTAL = 191488
};

// global scratch for pre-split K (3-way) and V (2-way): 5 x 16.8 MB
__device__ uint4 g_KH[1048576], g_KM[1048576], g_KL[1048576];
__device__ uint4 g_VH[1048576], g_VL[1048576];

// ---------------------------------------------------------------------------
// JAX threefry2x32, key=(0,42); bits = x0 ^ x1 (validated R2)
// ---------------------------------------------------------------------------
__device__ __forceinline__ uint32_t rotl32(uint32_t x, int d) { return __funnelshift_l(x, x, d); }
__device__ __forceinline__ void tf_round(uint32_t& x0, uint32_t& x1, int r) {
    x0 += x1; x1 = rotl32(x1, r) ^ x0;
}
__device__ __forceinline__ uint32_t tf_bits(uint32_t idx) {
    const uint32_t ks0 = 0u, ks1 = 42u, ks2 = 0x1BD11BDAu ^ 42u;
    uint32_t x0 = 0u, x1 = idx;
    x0 += ks0; x1 += ks1;
    tf_round(x0, x1, 13); tf_round(x0, x1, 15); tf_round(x0, x1, 26); tf_round(x0, x1, 6);
    x0 += ks1; x1 += ks2 + 1u;
    tf_round(x0, x1, 17); tf_round(x0, x1, 29); tf_round(x0, x1, 16); tf_round(x0, x1, 24);
    x0 += ks2; x1 += ks0 + 2u;
    tf_round(x0, x1, 13); tf_round(x0, x1, 15); tf_round(x0, x1, 26); tf_round(x0, x1, 6);
    x0 += ks0; x1 += ks1 + 3u;
    tf_round(x0, x1, 17); tf_round(x0, x1, 29); tf_round(x0, x1, 16); tf_round(x0, x1, 24);
    x0 += ks1; x1 += ks2 + 4u;
    tf_round(x0, x1, 13); tf_round(x0, x1, 15); tf_round(x0, x1, 26); tf_round(x0, x1, 6);
    x0 += ks2; x1 += ks0 + 5u;
    return x0 ^ x1;
}

__device__ __forceinline__ uint32_t pack2(__nv_bfloat16 a, __nv_bfloat16 b) {
    return (uint32_t)__bfloat16_as_ushort(a) | ((uint32_t)__bfloat16_as_ushort(b) << 16);
}
__device__ __forceinline__ uint32_t packf2(float lo, float hi) {
    uint32_t d;
    asm("cvt.rn.bf16x2.f32 %0, %1, %2;" : "=r"(d) : "f"(hi), "f"(lo));
    return d;
}
__device__ __forceinline__ void split3(float x, __nv_bfloat16& h, __nv_bfloat16& m,
                                       __nv_bfloat16& l) {
    h = __float2bfloat16(x);
    float rm = x - __bfloat162float(h);
    m = __float2bfloat16(rm);
    l = __float2bfloat16(rm - __bfloat162float(m));
}
__device__ __forceinline__ void split2(float x, __nv_bfloat16& h, __nv_bfloat16& l) {
    h = __float2bfloat16(x);
    l = __float2bfloat16(x - __bfloat162float(h));
}

__device__ __forceinline__ uint32_t smem_u32(const void* p) {
    uint32_t a;
    asm("{ .reg .u64 t; cvta.to.shared.u64 t, %1; cvt.u32.u64 %0, t; }" : "=r"(a) : "l"(p));
    return a;
}

__device__ __forceinline__ void mma16816(float c[4], const uint32_t a[4], const uint32_t b[2]) {
    asm volatile("mma.sync.aligned.m16n8k16.row.col.f32.bf16.bf16.f32 "
        "{%0,%1,%2,%3}, {%4,%5,%6,%7}, {%8,%9}, {%0,%1,%2,%3};"
        : "+f"(c[0]), "+f"(c[1]), "+f"(c[2]), "+f"(c[3])
        : "r"(a[0]), "r"(a[1]), "r"(a[2]), "r"(a[3]), "r"(b[0]), "r"(b[1]));
}
__device__ __forceinline__ void ldsm4(uint32_t r[4], uint32_t addr) {
    asm volatile("ldmatrix.sync.aligned.m8n8.x4.shared.b16 {%0,%1,%2,%3}, [%4];"
        : "=r"(r[0]), "=r"(r[1]), "=r"(r[2]), "=r"(r[3]) : "r"(addr));
}
__device__ __forceinline__ void ldsm4t(uint32_t r[4], uint32_t addr) {
    asm volatile("ldmatrix.sync.aligned.m8n8.x4.trans.shared.b16 {%0,%1,%2,%3}, [%4];"
        : "=r"(r[0]), "=r"(r[1]), "=r"(r[2]), "=r"(r[3]) : "r"(addr));
}

// ---------------------------------------------------------------------------
// Prep: split K (3-way) and V (2-way) into global bf16 planes
// ---------------------------------------------------------------------------
#define NK4 2097152   // B*Skv*D/4
__global__ void __launch_bounds__(256) prep_kernel(const float* __restrict__ k,
                                                   const float* __restrict__ v) {
    int i = blockIdx.x * 256 + threadIdx.x;
    if (i < NK4) {
        float4 x = ((const float4*)k)[i];
        __nv_bfloat16 h[4], m[4], l[4];
        split3(x.x, h[0], m[0], l[0]); split3(x.y, h[1], m[1], l[1]);
        split3(x.z, h[2], m[2], l[2]); split3(x.w, h[3], m[3], l[3]);
        ((uint2*)g_KH)[i] = make_uint2(pack2(h[0], h[1]), pack2(h[2], h[3]));
        ((uint2*)g_KM)[i] = make_uint2(pack2(m[0], m[1]), pack2(m[2], m[3]));
        ((uint2*)g_KL)[i] = make_uint2(pack2(l[0], l[1]), pack2(l[2], l[3]));
    } else {
        int j = i - NK4;
        float4 x = ((const float4*)v)[j];
        __nv_bfloat16 h[4], l[4];
        split2(x.x, h[0], l[0]); split2(x.y, h[1], l[1]);
        split2(x.z, h[2], l[2]); split2(x.w, h[3], l[3]);
        ((uint2*)g_VH)[j] = make_uint2(pack2(h[0], h[1]), pack2(h[2], h[3]));
        ((uint2*)g_VL)[j] = make_uint2(pack2(l[0], l[1]), pack2(l[2], l[3]));
    }
}

// ---------------------------------------------------------------------------
// Main attention kernel
// ---------------------------------------------------------------------------
__global__ void __launch_bounds__(NTHREADS, 1)
attn_fa2_kernel(const float* __restrict__ q,
                const float* __restrict__ sf,
                float* __restrict__ out) {
    extern __shared__ char smem[];
    const uint32_t sb = smem_u32(smem);

    const int b    = blockIdx.y;
    const int q0   = blockIdx.x * MT;
    const int tid  = threadIdx.x;
    const int w    = tid >> 5;
    const int lane = tid & 31;
    const int g    = lane >> 2;
    const int tig  = lane & 3;
    const int m0   = w * 16;
    const int l7   = lane & 7;
    const int b3   = (lane >> 3) & 1;
    const int b4   = lane >> 4;

    // per-lane ldmatrix base addresses (byte)
    const uint32_t aBase = sb + OFF_QH + (uint32_t)((m0 + l7 + 8 * b3) * ROWB + 16 * b4);
    const uint32_t kBase = sb + OFF_KH + (uint32_t)((l7 + 8 * b4) * ROWB + 16 * b3);
    const uint32_t vBase = sb + OFF_VH + (uint32_t)((l7 + 8 * b3) * ROWB + 16 * b4);

    // ---- stage Q (scale folded), 3-way split ----
    {
        const float scale = sf[b];
        const float4* qg4 = (const float4*)(q + ((long)(b * SQ_ + q0)) * D_);
        for (int f = tid; f < MT * D_ / 4; f += NTHREADS) {
            int rr = f >> 5, c = (f & 31) * 4;
            float4 x = qg4[f];
            float xs[4] = {x.x * scale, x.y * scale, x.z * scale, x.w * scale};
            __nv_bfloat16 h[4], m[4], l[4];
#pragma unroll
            for (int j = 0; j < 4; j++) split3(xs[j], h[j], m[j], l[j]);
            uint32_t idx = rr * SKQ + c;
            *(uint2*)((__nv_bfloat16*)(smem + OFF_QH) + idx) = make_uint2(pack2(h[0], h[1]), pack2(h[2], h[3]));
            *(uint2*)((__nv_bfloat16*)(smem + OFF_QM) + idx) = make_uint2(pack2(m[0], m[1]), pack2(m[2], m[3]));
            *(uint2*)((__nv_bfloat16*)(smem + OFF_QL) + idx) = make_uint2(pack2(l[0], l[1]), pack2(l[2], l[3]));
        }
    }

    float O[16][4];
#pragma unroll
    for (int nt = 0; nt < 16; nt++) { O[nt][0] = O[nt][1] = O[nt][2] = O[nt][3] = 0.0f; }
    float mr0 = -3.402823466e38f, mr1 = -3.402823466e38f, lr0 = 0.0f, lr1 = 0.0f;

    const uint32_t rowbase = (uint32_t)(b * SQ_ + q0 + m0);

    for (int t = 0; t < NTILES; t++) {
        const int kv0 = t * NT;
        const int bk  = b * SKV_ + kv0;   // global row base for this tile
        __syncthreads();

        // ---- stage pre-split K/V: pure LDG.128 -> STS.128 ----
        {
            const uint4* gk[3] = {g_KH, g_KM, g_KL};
#pragma unroll
            for (int s = 0; s < 3; s++)
#pragma unroll
                for (int c = 0; c < 4; c++) {
                    int f = tid + 256 * c;
                    int rr = f >> 4, c4 = f & 15;
                    uint4 val = gk[s][(bk + rr) * 16 + c4];
                    *(uint4*)(smem + OFF_KH + s * 17408 + rr * ROWB + c4 * 16) = val;
                }
            const uint4* gv[2] = {g_VH, g_VL};
#pragma unroll
            for (int s = 0; s < 2; s++)
#pragma unroll
                for (int c = 0; c < 4; c++) {
                    int f = tid + 256 * c;
                    int rr = f >> 4, c4 = f & 15;
                    uint4 val = gv[s][(bk + rr) * 16 + c4];
                    *(uint4*)(smem + OFF_VH + s * 17408 + rr * ROWB + c4 * 16) = val;
                }
        }
        __syncthreads();

        // ---- QK MMAs with threefry mask interleaved ----
        float sacc[8][4];
#pragma unroll
        for (int nt = 0; nt < 8; nt++) { sacc[nt][0] = sacc[nt][1] = sacc[nt][2] = sacc[nt][3] = 0.0f; }

        uint32_t kmask = 0;
        const uint32_t idx00 = (rowbase + (uint32_t)g) * (uint32_t)SKV_
                             + (uint32_t)(kv0 + 2 * tig);

#pragma unroll
        for (int k8 = 0; k8 < 8; k8++) {
            // dropout mask for n-tile k8 (independent of S -> overlaps HMMA)
            {
                uint32_t ia = idx00 + (uint32_t)(8 * k8);
                uint32_t ib = ia + 8u * (uint32_t)SKV_;
                uint32_t m0b = (tf_bits(ia)      < KEEP_THRESH) ? 1u : 0u;
                uint32_t m1b = (tf_bits(ia + 1u) < KEEP_THRESH) ? 2u : 0u;
                uint32_t m2b = (tf_bits(ib)      < KEEP_THRESH) ? 4u : 0u;
                uint32_t m3b = (tf_bits(ib + 1u) < KEEP_THRESH) ? 8u : 0u;
                kmask |= (m0b | m1b | m2b | m3b) << (4 * k8);
            }

            uint32_t aH[4], aM[4], aL[4];
            const uint32_t aAddr = aBase + (uint32_t)(k8 * 32);
            ldsm4(aH, aAddr);
            ldsm4(aM, aAddr + 34816u);
            ldsm4(aL, aAddr + 69632u);
#pragma unroll
            for (int ntp = 0; ntp < 4; ntp++) {
                const uint32_t kAddr = kBase + (uint32_t)(ntp * 16 * ROWB + k8 * 32);
                uint32_t kH[4], kM[4], kL[4];
                ldsm4(kH, kAddr);
                ldsm4(kM, kAddr + 17408u);
                ldsm4(kL, kAddr + 34816u);
                mma16816(sacc[2 * ntp], aH, kH);
                mma16816(sacc[2 * ntp], aH, kM);
                mma16816(sacc[2 * ntp], aM, kH);
                mma16816(sacc[2 * ntp], aH, kL);
                mma16816(sacc[2 * ntp], aL, kH);
                mma16816(sacc[2 * ntp], aM, kM);
                mma16816(sacc[2 * ntp + 1], aH, kH + 2);
                mma16816(sacc[2 * ntp + 1], aH, kM + 2);
                mma16816(sacc[2 * ntp + 1], aM, kH + 2);
                mma16816(sacc[2 * ntp + 1], aH, kL + 2);
                mma16816(sacc[2 * ntp + 1], aL, kH + 2);
                mma16816(sacc[2 * ntp + 1], aM, kM + 2);
            }
        }

        // ---- softmax + dropout (mask precomputed), all intra-warp ----
        float mx0 = sacc[0][0], mx1 = sacc[0][2];
#pragma unroll
        for (int nt = 0; nt < 8; nt++) {
            mx0 = fmaxf(mx0, fmaxf(sacc[nt][0], sacc[nt][1]));
            mx1 = fmaxf(mx1, fmaxf(sacc[nt][2], sacc[nt][3]));
        }
        mx0 = fmaxf(mx0, __shfl_xor_sync(0xffffffffu, mx0, 1));
        mx0 = fmaxf(mx0, __shfl_xor_sync(0xffffffffu, mx0, 2));
        mx1 = fmaxf(mx1, __shfl_xor_sync(0xffffffffu, mx1, 1));
        mx1 = fmaxf(mx1, __shfl_xor_sync(0xffffffffu, mx1, 2));
        float mn0 = fmaxf(mr0, mx0), mn1 = fmaxf(mr1, mx1);
        float al0 = exp2f((mr0 - mn0) * LOG2E_F);
        float al1 = exp2f((mr1 - mn1) * LOG2E_F);

        uint32_t pHa[8], pHb[8], pLa[8], pLb[8];
        float ls0 = 0.0f, ls1 = 0.0f;
#pragma unroll
        for (int nt = 0; nt < 8; nt++) {
            float p0 = exp2f((sacc[nt][0] - mn0) * LOG2E_F);
            float p1 = exp2f((sacc[nt][1] - mn0) * LOG2E_F);
            float p2 = exp2f((sacc[nt][2] - mn1) * LOG2E_F);
            float p3 = exp2f((sacc[nt][3] - mn1) * LOG2E_F);
            ls0 += p0 + p1; ls1 += p2 + p3;
            uint32_t mb = kmask >> (4 * nt);
            float d0 = (mb & 1u) ? p0 * INV_KEEP : 0.0f;
            float d1 = (mb & 2u) ? p1 * INV_KEEP : 0.0f;
            float d2 = (mb & 4u) ? p2 * INV_KEEP : 0.0f;
            float d3 = (mb & 8u) ? p3 * INV_KEEP : 0.0f;
            pHa[nt] = packf2(d0, d1);
            pHb[nt] = packf2(d2, d3);
            float r0 = d0 - __bfloat162float(__float2bfloat16(d0));
            float r1 = d1 - __bfloat162float(__float2bfloat16(d1));
            float r2 = d2 - __bfloat162float(__float2bfloat16(d2));
            float r3 = d3 - __bfloat162float(__float2bfloat16(d3));
            pLa[nt] = packf2(r0, r1);
            pLb[nt] = packf2(r2, r3);
        }
        ls0 += __shfl_xor_sync(0xffffffffu, ls0, 1);
        ls0 += __shfl_xor_sync(0xffffffffu, ls0, 2);
        ls1 += __shfl_xor_sync(0xffffffffu, ls1, 1);
        ls1 += __shfl_xor_sync(0xffffffffu, ls1, 2);
        lr0 = lr0 * al0 + ls0;
        lr1 = lr1 * al1 + ls1;
        mr0 = mn0; mr1 = mn1;

#pragma unroll
        for (int nt = 0; nt < 16; nt++) {
            O[nt][0] *= al0; O[nt][1] *= al0;
            O[nt][2] *= al1; O[nt][3] *= al1;
        }

        // ---- PV: O += P * V  (P regs; V via ldmatrix.trans) ----
#pragma unroll
        for (int kkp = 0; kkp < 4; kkp++) {
            uint32_t aH[4] = { pHa[2 * kkp], pHb[2 * kkp], pHa[2 * kkp + 1], pHb[2 * kkp + 1] };
            uint32_t aL[4] = { pLa[2 * kkp], pLb[2 * kkp], pLa[2 * kkp + 1], pLb[2 * kkp + 1] };
#pragma unroll
            for (int ntp = 0; ntp < 8; ntp++) {
                const uint32_t vAddr = vBase + (uint32_t)(kkp * 16 * ROWB + ntp * 32);
                uint32_t vH[4], vL[4];
                ldsm4t(vH, vAddr);
                ldsm4t(vL, vAddr + 17408u);
                mma16816(O[2 * ntp], aH, vH);
                mma16816(O[2 * ntp], aH, vL);
                mma16816(O[2 * ntp], aL, vH);
                mma16816(O[2 * ntp + 1], aH, vH + 2);
                mma16816(O[2 * ntp + 1], aH, vL + 2);
                mma16816(O[2 * ntp + 1], aL, vH + 2);
            }
        }
    }

    // ---- final: O / l -> gmem ----
    {
        float inv0 = 1.0f / lr0, inv1 = 1.0f / lr1;
        long row0 = (long)(b * SQ_ + q0 + m0 + g);
        float* o0 = out + row0 * D_ + 2 * tig;
        float* o1 = out + (row0 + 8) * D_ + 2 * tig;
#pragma unroll
        for (int nt = 0; nt < 16; nt++) {
            *(float2*)(o0 + 8 * nt) = make_float2(O[nt][0] * inv0, O[nt][1] * inv0);
            *(float2*)(o1 + 8 * nt) = make_float2(O[nt][2] * inv1, O[nt][3] * inv1);
        }
    }
}

// ---------------------------------------------------------------------------
extern "C" void kernel_launch(void* const* d_in, const int* in_sizes, int n_in,
                              void* d_out, int out_size) {
    const float* q  = (const float*)d_in[0];
    const float* k  = (const float*)d_in[1];
    const float* v  = (const float*)d_in[2];
    const float* sf = (const float*)d_in[3];
    float* out = (float*)d_out;

    prep_kernel<<<2 * NK4 / 256, 256>>>(k, v);

    cudaFuncSetAttribute(attn_fa2_kernel,
                         cudaFuncAttributeMaxDynamicSharedMemorySize, SMEM_TOTAL);
    dim3 grid(SQ_ / MT, B_);
    attn_fa2_kernel<<<grid, NTHREADS, SMEM_TOTAL>>>(q, sf, out);
}

// round 10
// speedup vs baseline: 2.3743x; 1.2573x over previous
#include <cuda_runtime.h>
#include <cuda_fp16.h>
#include <cstdint>

#define B_    32
#define SQ_   2048
#define SKV_  2048
#define D_    128
#define MT    128
#define NT    64
#define NTILES (SKV_/NT)
#define NTHREADS 256

#define INV_KEEP  (1.0f/0.7f)
#define LOG2E_F   1.4426950408889634f
// keep <=> tf_bits < KEEP_THRESH (exact integer form of u < 0.7f, validated R9)
#define KEEP_THRESH 0xB3333400u

#define ROWB 272          // row stride bytes (136 fp16) -> LDSM conflict-free

enum {
  OFF_QH = 0, OFF_QL = 34816,                    // Q planes: 128*272
  OFF_BUF0 = 69632, OFF_BUF1 = 139264,           // K/V double buffer
  BUF_KH = 0, BUF_KL = 17408, BUF_VH = 34816, BUF_VL = 52224,  // within buffer
  SMEM_TOTAL = 208896
};

// global scratch: fp16 2-way split planes (prep kernel fills once per launch)
#define NV4 1048576   // uint4 per plane (B*S*D fp16 = 16 MB)
__device__ uint4 g_QH[NV4], g_QL[NV4];
__device__ uint4 g_KH[NV4], g_KL[NV4];
__device__ uint4 g_VH[NV4], g_VL[NV4];

// ---------------------------------------------------------------------------
// JAX threefry2x32, key=(0,42); bits = x0 ^ x1 (validated R2)
// ---------------------------------------------------------------------------
__device__ __forceinline__ uint32_t rotl32(uint32_t x, int d) { return __funnelshift_l(x, x, d); }
__device__ __forceinline__ void tf_round(uint32_t& x0, uint32_t& x1, int r) {
    x0 += x1; x1 = rotl32(x1, r) ^ x0;
}
__device__ __forceinline__ uint32_t tf_bits(uint32_t idx) {
    const uint32_t ks0 = 0u, ks1 = 42u, ks2 = 0x1BD11BDAu ^ 42u;
    uint32_t x0 = 0u, x1 = idx;
    x0 += ks0; x1 += ks1;
    tf_round(x0, x1, 13); tf_round(x0, x1, 15); tf_round(x0, x1, 26); tf_round(x0, x1, 6);
    x0 += ks1; x1 += ks2 + 1u;
    tf_round(x0, x1, 17); tf_round(x0, x1, 29); tf_round(x0, x1, 16); tf_round(x0, x1, 24);
    x0 += ks2; x1 += ks0 + 2u;
    tf_round(x0, x1, 13); tf_round(x0, x1, 15); tf_round(x0, x1, 26); tf_round(x0, x1, 6);
    x0 += ks0; x1 += ks1 + 3u;
    tf_round(x0, x1, 17); tf_round(x0, x1, 29); tf_round(x0, x1, 16); tf_round(x0, x1, 24);
    x0 += ks1; x1 += ks2 + 4u;
    tf_round(x0, x1, 13); tf_round(x0, x1, 15); tf_round(x0, x1, 26); tf_round(x0, x1, 6);
    x0 += ks2; x1 += ks0 + 5u;
    return x0 ^ x1;
}

__device__ __forceinline__ uint32_t pack2h(__half a, __half b) {
    return (uint32_t)__half_as_ushort(a) | ((uint32_t)__half_as_ushort(b) << 16);
}
__device__ __forceinline__ uint32_t packh2(float lo, float hi) {
    uint32_t d;
    asm("cvt.rn.f16x2.f32 %0, %1, %2;" : "=r"(d) : "f"(hi), "f"(lo));
    return d;
}
__device__ __forceinline__ void split2h(float x, __half& h, __half& l) {
    h = __float2half_rn(x);
    l = __float2half_rn(x - __half2float(h));
}

__device__ __forceinline__ uint32_t smem_u32(const void* p) {
    uint32_t a;
    asm("{ .reg .u64 t; cvta.to.shared.u64 t, %1; cvt.u32.u64 %0, t; }" : "=r"(a) : "l"(p));
    return a;
}
__device__ __forceinline__ void mma_h(float c[4], const uint32_t a[4], const uint32_t b[2]) {
    asm volatile("mma.sync.aligned.m16n8k16.row.col.f32.f16.f16.f32 "
        "{%0,%1,%2,%3}, {%4,%5,%6,%7}, {%8,%9}, {%0,%1,%2,%3};"
        : "+f"(c[0]), "+f"(c[1]), "+f"(c[2]), "+f"(c[3])
        : "r"(a[0]), "r"(a[1]), "r"(a[2]), "r"(a[3]), "r"(b[0]), "r"(b[1]));
}
__device__ __forceinline__ void ldsm4(uint32_t r[4], uint32_t addr) {
    asm volatile("ldmatrix.sync.aligned.m8n8.x4.shared.b16 {%0,%1,%2,%3}, [%4];"
        : "=r"(r[0]), "=r"(r[1]), "=r"(r[2]), "=r"(r[3]) : "r"(addr));
}
__device__ __forceinline__ void ldsm4t(uint32_t r[4], uint32_t addr) {
    asm volatile("ldmatrix.sync.aligned.m8n8.x4.trans.shared.b16 {%0,%1,%2,%3}, [%4];"
        : "=r"(r[0]), "=r"(r[1]), "=r"(r[2]), "=r"(r[3]) : "r"(addr));
}
__device__ __forceinline__ void cpasync16(uint32_t dst, const void* src) {
    asm volatile("cp.async.cg.shared.global [%0], [%1], 16;" :: "r"(dst), "l"(src));
}
#define CP_COMMIT() asm volatile("cp.async.commit_group;" ::: "memory")
#define CP_WAIT1()  asm volatile("cp.async.wait_group 1;" ::: "memory")
#define CP_WAIT0()  asm volatile("cp.async.wait_group 0;" ::: "memory")

// ---------------------------------------------------------------------------
// Prep: fp16 2-way split of Q (scale folded), K, V into global planes
// ---------------------------------------------------------------------------
#define NQ4 2097152   // float4 per tensor
__global__ void __launch_bounds__(256) prep_kernel(const float* __restrict__ q,
                                                   const float* __restrict__ k,
                                                   const float* __restrict__ v,
                                                   const float* __restrict__ sf) {
    int i = blockIdx.x * 256 + threadIdx.x;
    float4 x;
    uint2 *dh, *dl;
    int j;
    if (i < NQ4) {
        x = ((const float4*)q)[i];
        float s = sf[i >> 16];            // Sq*D/4 = 65536 float4 per batch
        x.x *= s; x.y *= s; x.z *= s; x.w *= s;
        dh = (uint2*)g_QH; dl = (uint2*)g_QL; j = i;
    } else if (i < 2 * NQ4) {
        j = i - NQ4;
        x = ((const float4*)k)[j];
        dh = (uint2*)g_KH; dl = (uint2*)g_KL;
    } else {
        j = i - 2 * NQ4;
        x = ((const float4*)v)[j];
        dh = (uint2*)g_VH; dl = (uint2*)g_VL;
    }
    __half h[4], l[4];
    split2h(x.x, h[0], l[0]); split2h(x.y, h[1], l[1]);
    split2h(x.z, h[2], l[2]); split2h(x.w, h[3], l[3]);
    dh[j] = make_uint2(pack2h(h[0], h[1]), pack2h(h[2], h[3]));
    dl[j] = make_uint2(pack2h(l[0], l[1]), pack2h(l[2], l[3]));
}

// ---------------------------------------------------------------------------
// Main attention kernel
// ---------------------------------------------------------------------------
__global__ void __launch_bounds__(NTHREADS, 1)
attn_fa3_kernel(float* __restrict__ out) {
    extern __shared__ char smem[];
    const uint32_t sb = smem_u32(smem);

    const int b    = blockIdx.y;
    const int q0   = blockIdx.x * MT;
    const int tid  = threadIdx.x;
    const int w    = tid >> 5;
    const int lane = tid & 31;
    const int g    = lane >> 2;
    const int tig  = lane & 3;
    const int m0   = w * 16;
    const int l7   = lane & 7;
    const int b3   = (lane >> 3) & 1;
    const int b4   = lane >> 4;

    const uint32_t aBase   = sb + OFF_QH + (uint32_t)((m0 + l7 + 8 * b3) * ROWB + 16 * b4);
    const uint32_t kLaneOf = (uint32_t)((l7 + 8 * b4) * ROWB + 16 * b3);
    const uint32_t vLaneOf = (uint32_t)((l7 + 8 * b3) * ROWB + 16 * b4);

    // ---- stage Q planes (pure LDG.128 -> STS.128) ----
    {
        const int qrow0 = (b * SQ_ + q0) * 16;   // uint4 row base (16 per row)
#pragma unroll
        for (int c = 0; c < 8; c++) {
            int f = tid + 256 * c;
            int rr = f >> 4, c4 = f & 15;
            *(uint4*)(smem + OFF_QH + rr * ROWB + c4 * 16) = g_QH[qrow0 + rr * 16 + c4];
            *(uint4*)(smem + OFF_QL + rr * ROWB + c4 * 16) = g_QL[qrow0 + rr * 16 + c4];
        }
    }

    float O[16][4];
#pragma unroll
    for (int nt = 0; nt < 16; nt++) { O[nt][0] = O[nt][1] = O[nt][2] = O[nt][3] = 0.0f; }
    float mr0 = -3.402823466e38f, mr1 = -3.402823466e38f, lr0 = 0.0f, lr1 = 0.0f;

    const uint32_t rowbase = (uint32_t)(b * SQ_ + q0 + m0);
    const int bkb = b * SKV_;   // global kv row base for this batch

    // prologue: stage tile 0 into buf0
    {
        const uint4* gp[4] = {g_KH, g_KL, g_VH, g_VL};
#pragma unroll
        for (int s = 0; s < 4; s++)
#pragma unroll
            for (int c = 0; c < 4; c++) {
                int f = tid + 256 * c;
                int rr = f >> 4, c4 = f & 15;
                cpasync16(sb + OFF_BUF0 + (uint32_t)(s * 17408 + rr * ROWB + c4 * 16),
                          &gp[s][(bkb + rr) * 16 + c4]);
            }
        CP_COMMIT();
    }

    for (int t = 0; t < NTILES; t++) {
        const int kv0 = t * NT;
        __syncthreads();   // prior compute done reading the buffer we're about to fill

        if (t + 1 < NTILES) {
            const uint32_t nbuf = sb + (((t + 1) & 1) ? OFF_BUF1 : OFF_BUF0);
            const int bk = bkb + (t + 1) * NT;
            const uint4* gp[4] = {g_KH, g_KL, g_VH, g_VL};
#pragma unroll
            for (int s = 0; s < 4; s++)
#pragma unroll
                for (int c = 0; c < 4; c++) {
                    int f = tid + 256 * c;
                    int rr = f >> 4, c4 = f & 15;
                    cpasync16(nbuf + (uint32_t)(s * 17408 + rr * ROWB + c4 * 16),
                              &gp[s][(bk + rr) * 16 + c4]);
                }
            CP_COMMIT();
            CP_WAIT1();
        } else {
            CP_WAIT0();
        }
        __syncthreads();   // all threads' cp.async for tile t visible

        const uint32_t bufb  = sb + ((t & 1) ? OFF_BUF1 : OFF_BUF0);
        const uint32_t kBase = bufb + BUF_KH + kLaneOf;
        const uint32_t vBase = bufb + BUF_VH + vLaneOf;

        // ---- QK MMAs (4 fp16 passes) with threefry mask interleaved ----
        float sacc[8][4];
#pragma unroll
        for (int nt = 0; nt < 8; nt++) { sacc[nt][0] = sacc[nt][1] = sacc[nt][2] = sacc[nt][3] = 0.0f; }

        uint32_t kmask = 0;
        const uint32_t idx00 = (rowbase + (uint32_t)g) * (uint32_t)SKV_
                             + (uint32_t)(kv0 + 2 * tig);

#pragma unroll
        for (int k8 = 0; k8 < 8; k8++) {
            {   // dropout mask for n-tile k8 (ALU, overlaps HMMA)
                uint32_t ia = idx00 + (uint32_t)(8 * k8);
                uint32_t ib = ia + 8u * (uint32_t)SKV_;
                uint32_t q0b = (tf_bits(ia)      < KEEP_THRESH) ? 1u : 0u;
                uint32_t q1b = (tf_bits(ia + 1u) < KEEP_THRESH) ? 2u : 0u;
                uint32_t q2b = (tf_bits(ib)      < KEEP_THRESH) ? 4u : 0u;
                uint32_t q3b = (tf_bits(ib + 1u) < KEEP_THRESH) ? 8u : 0u;
                kmask |= (q0b | q1b | q2b | q3b) << (4 * k8);
            }
            uint32_t aH[4], aL[4];
            const uint32_t aAddr = aBase + (uint32_t)(k8 * 32);
            ldsm4(aH, aAddr);
            ldsm4(aL, aAddr + 34816u);
#pragma unroll
            for (int ntp = 0; ntp < 4; ntp++) {
                const uint32_t kAddr = kBase + (uint32_t)(ntp * 16 * ROWB + k8 * 32);
                uint32_t kH[4], kL[4];
                ldsm4(kH, kAddr);
                ldsm4(kL, kAddr + 17408u);
                mma_h(sacc[2 * ntp], aH, kH);
                mma_h(sacc[2 * ntp], aH, kL);
                mma_h(sacc[2 * ntp], aL, kH);
                mma_h(sacc[2 * ntp], aL, kL);
                mma_h(sacc[2 * ntp + 1], aH, kH + 2);
                mma_h(sacc[2 * ntp + 1], aH, kL + 2);
                mma_h(sacc[2 * ntp + 1], aL, kH + 2);
                mma_h(sacc[2 * ntp + 1], aL, kL + 2);
            }
        }

        // ---- softmax + dropout (mask precomputed), intra-warp ----
        float mx0 = sacc[0][0], mx1 = sacc[0][2];
#pragma unroll
        for (int nt = 0; nt < 8; nt++) {
            mx0 = fmaxf(mx0, fmaxf(sacc[nt][0], sacc[nt][1]));
            mx1 = fmaxf(mx1, fmaxf(sacc[nt][2], sacc[nt][3]));
        }
        mx0 = fmaxf(mx0, __shfl_xor_sync(0xffffffffu, mx0, 1));
        mx0 = fmaxf(mx0, __shfl_xor_sync(0xffffffffu, mx0, 2));
        mx1 = fmaxf(mx1, __shfl_xor_sync(0xffffffffu, mx1, 1));
        mx1 = fmaxf(mx1, __shfl_xor_sync(0xffffffffu, mx1, 2));
        float mn0 = fmaxf(mr0, mx0), mn1 = fmaxf(mr1, mx1);
        float al0 = exp2f((mr0 - mn0) * LOG2E_F);
        float al1 = exp2f((mr1 - mn1) * LOG2E_F);

        uint32_t pHa[8], pHb[8], pLa[8], pLb[8];
        float ls0 = 0.0f, ls1 = 0.0f;
#pragma unroll
        for (int nt = 0; nt < 8; nt++) {
            float p0 = exp2f((sacc[nt][0] - mn0) * LOG2E_F);
            float p1 = exp2f((sacc[nt][1] - mn0) * LOG2E_F);
            float p2 = exp2f((sacc[nt][2] - mn1) * LOG2E_F);
            float p3 = exp2f((sacc[nt][3] - mn1) * LOG2E_F);
            ls0 += p0 + p1; ls1 += p2 + p3;
            uint32_t mb = kmask >> (4 * nt);
            float d0 = (mb & 1u) ? p0 * INV_KEEP : 0.0f;
            float d1 = (mb & 2u) ? p1 * INV_KEEP : 0.0f;
            float d2 = (mb & 4u) ? p2 * INV_KEEP : 0.0f;
            float d3 = (mb & 8u) ? p3 * INV_KEEP : 0.0f;
            pHa[nt] = packh2(d0, d1);
            pHb[nt] = packh2(d2, d3);
            float r0 = d0 - __half2float(__float2half_rn(d0));
            float r1 = d1 - __half2float(__float2half_rn(d1));
            float r2 = d2 - __half2float(__float2half_rn(d2));
            float r3 = d3 - __half2float(__float2half_rn(d3));
            pLa[nt] = packh2(r0, r1);
            pLb[nt] = packh2(r2, r3);
        }
        ls0 += __shfl_xor_sync(0xffffffffu, ls0, 1);
        ls0 += __shfl_xor_sync(0xffffffffu, ls0, 2);
        ls1 += __shfl_xor_sync(0xffffffffu, ls1, 1);
        ls1 += __shfl_xor_sync(0xffffffffu, ls1, 2);
        lr0 = lr0 * al0 + ls0;
        lr1 = lr1 * al1 + ls1;
        mr0 = mn0; mr1 = mn1;

#pragma unroll
        for (int nt = 0; nt < 16; nt++) {
            O[nt][0] *= al0; O[nt][1] *= al0;
            O[nt][2] *= al1; O[nt][3] *= al1;
        }

        // ---- PV: O += P * V (3 fp16 passes; V via ldmatrix.trans) ----
#pragma unroll
        for (int kkp = 0; kkp < 4; kkp++) {
            uint32_t aH[4] = { pHa[2 * kkp], pHb[2 * kkp], pHa[2 * kkp + 1], pHb[2 * kkp + 1] };
            uint32_t aL[4] = { pLa[2 * kkp], pLb[2 * kkp], pLa[2 * kkp + 1], pLb[2 * kkp + 1] };
#pragma unroll
            for (int ntp = 0; ntp < 8; ntp++) {
                const uint32_t vAddr = vBase + (uint32_t)(kkp * 16 * ROWB + ntp * 32);
                uint32_t vH[4], vL[4];
                ldsm4t(vH, vAddr);
                ldsm4t(vL, vAddr + 17408u);
                mma_h(O[2 * ntp], aH, vH);
                mma_h(O[2 * ntp], aH, vL);
                mma_h(O[2 * ntp], aL, vH);
                mma_h(O[2 * ntp + 1], aH, vH + 2);
                mma_h(O[2 * ntp + 1], aH, vL + 2);
                mma_h(O[2 * ntp + 1], aL, vH + 2);
            }
        }
    }

    // ---- final: O / l -> gmem ----
    {
        float inv0 = 1.0f / lr0, inv1 = 1.0f / lr1;
        long row0 = (long)(b * SQ_ + q0 + m0 + g);
        float* o0 = out + row0 * D_ + 2 * tig;
        float* o1 = out + (row0 + 8) * D_ + 2 * tig;
#pragma unroll
        for (int nt = 0; nt < 16; nt++) {
            *(float2*)(o0 + 8 * nt) = make_float2(O[nt][0] * inv0, O[nt][1] * inv0);
            *(float2*)(o1 + 8 * nt) = make_float2(O[nt][2] * inv1, O[nt][3] * inv1);
        }
    }
}

// ---------------------------------------------------------------------------
extern "C" void kernel_launch(void* const* d_in, const int* in_sizes, int n_in,
                              void* d_out, int out_size) {
    const float* q  = (const float*)d_in[0];
    const float* k  = (const float*)d_in[1];
    const float* v  = (const float*)d_in[2];
    const float* sf = (const float*)d_in[3];
    float* out = (float*)d_out;

    prep_kernel<<<3 * NQ4 / 256, 256>>>(q, k, v, sf);

    cudaFuncSetAttribute(attn_fa3_kernel,
                         cudaFuncAttributeMaxDynamicSharedMemorySize, SMEM_TOTAL);
    dim3 grid(SQ_ / MT, B_);
    attn_fa3_kernel<<<grid, NTHREADS, SMEM_TOTAL>>>(out);
}

// round 11
// speedup vs baseline: 2.7086x; 1.1408x over previous
#include <cuda_runtime.h>
#include <cuda_fp16.h>
#include <cstdint>

#define B_    32
#define SQ_   2048
#define SKV_  2048
#define D_    128
#define MT    128
#define NT    64
#define NTILES (SKV_/NT)
#define NTHREADS 256

#define INV_KEEP  (1.0f/0.7f)
#define LOG2E_F   1.4426950408889634f
// keep <=> tf_bits < KEEP_THRESH (exact integer form of u < 0.7f, validated R9)
#define KEEP_THRESH 0xB3333400u

#define ROWB 272          // row stride bytes (136 fp16) -> LDSM conflict-free

enum {
  OFF_QH = 0, OFF_QL = 34816,                    // Q planes: 128*272
  OFF_BUF0 = 69632, OFF_BUF1 = 139264,           // K/V double buffer
  BUF_KH = 0, BUF_KL = 17408, BUF_VH = 34816, BUF_VL = 52224,
  SMEM_TOTAL = 208896
};

// global scratch: fp16 2-way split planes (prep kernel fills once per launch)
#define NV4 1048576
__device__ uint4 g_QH[NV4], g_QL[NV4];
__device__ uint4 g_KH[NV4], g_KL[NV4];
__device__ uint4 g_VH[NV4], g_VL[NV4];

// ---------------------------------------------------------------------------
// JAX threefry2x32, key=(0,42); bits = x0 ^ x1 (validated R2)
// ---------------------------------------------------------------------------
__device__ __forceinline__ uint32_t rotl32(uint32_t x, int d) { return __funnelshift_l(x, x, d); }
__device__ __forceinline__ void tf_round(uint32_t& x0, uint32_t& x1, int r) {
    x0 += x1; x1 = rotl32(x1, r) ^ x0;
}
__device__ __forceinline__ uint32_t tf_bits(uint32_t idx) {
    const uint32_t ks0 = 0u, ks1 = 42u, ks2 = 0x1BD11BDAu ^ 42u;
    uint32_t x0 = 0u, x1 = idx;
    x0 += ks0; x1 += ks1;
    tf_round(x0, x1, 13); tf_round(x0, x1, 15); tf_round(x0, x1, 26); tf_round(x0, x1, 6);
    x0 += ks1; x1 += ks2 + 1u;
    tf_round(x0, x1, 17); tf_round(x0, x1, 29); tf_round(x0, x1, 16); tf_round(x0, x1, 24);
    x0 += ks2; x1 += ks0 + 2u;
    tf_round(x0, x1, 13); tf_round(x0, x1, 15); tf_round(x0, x1, 26); tf_round(x0, x1, 6);
    x0 += ks0; x1 += ks1 + 3u;
    tf_round(x0, x1, 17); tf_round(x0, x1, 29); tf_round(x0, x1, 16); tf_round(x0, x1, 24);
    x0 += ks1; x1 += ks2 + 4u;
    tf_round(x0, x1, 13); tf_round(x0, x1, 15); tf_round(x0, x1, 26); tf_round(x0, x1, 6);
    x0 += ks2; x1 += ks0 + 5u;
    return x0 ^ x1;
}

__device__ __forceinline__ uint32_t pack2h(__half a, __half b) {
    return (uint32_t)__half_as_ushort(a) | ((uint32_t)__half_as_ushort(b) << 16);
}
__device__ __forceinline__ uint32_t packh2(float lo, float hi) {
    uint32_t d;
    asm("cvt.rn.f16x2.f32 %0, %1, %2;" : "=r"(d) : "f"(hi), "f"(lo));
    return d;
}
__device__ __forceinline__ void split2h(float x, __half& h, __half& l) {
    h = __float2half_rn(x);
    l = __float2half_rn(x - __half2float(h));
}

__device__ __forceinline__ uint32_t smem_u32(const void* p) {
    uint32_t a;
    asm("{ .reg .u64 t; cvta.to.shared.u64 t, %1; cvt.u32.u64 %0, t; }" : "=r"(a) : "l"(p));
    return a;
}
__device__ __forceinline__ void mma_h(float c[4], const uint32_t a[4], const uint32_t b[2]) {
    asm volatile("mma.sync.aligned.m16n8k16.row.col.f32.f16.f16.f32 "
        "{%0,%1,%2,%3}, {%4,%5,%6,%7}, {%8,%9}, {%0,%1,%2,%3};"
        : "+f"(c[0]), "+f"(c[1]), "+f"(c[2]), "+f"(c[3])
        : "r"(a[0]), "r"(a[1]), "r"(a[2]), "r"(a[3]), "r"(b[0]), "r"(b[1]));
}
__device__ __forceinline__ void ldsm4(uint32_t r[4], uint32_t addr) {
    asm volatile("ldmatrix.sync.aligned.m8n8.x4.shared.b16 {%0,%1,%2,%3}, [%4];"
        : "=r"(r[0]), "=r"(r[1]), "=r"(r[2]), "=r"(r[3]) : "r"(addr));
}
__device__ __forceinline__ void ldsm4t(uint32_t r[4], uint32_t addr) {
    asm volatile("ldmatrix.sync.aligned.m8n8.x4.trans.shared.b16 {%0,%1,%2,%3}, [%4];"
        : "=r"(r[0]), "=r"(r[1]), "=r"(r[2]), "=r"(r[3]) : "r"(addr));
}
__device__ __forceinline__ void cpasync16(uint32_t dst, const void* src) {
    asm volatile("cp.async.cg.shared.global [%0], [%1], 16;" :: "r"(dst), "l"(src));
}
#define CP_COMMIT() asm volatile("cp.async.commit_group;" ::: "memory")
#define CP_WAIT1()  asm volatile("cp.async.wait_group 1;" ::: "memory")
#define CP_WAIT0()  asm volatile("cp.async.wait_group 0;" ::: "memory")

// ---------------------------------------------------------------------------
// Prep: fp16 2-way split of Q (scale folded), K, V into global planes
// ---------------------------------------------------------------------------
#define NQ4 2097152
__global__ void __launch_bounds__(256) prep_kernel(const float* __restrict__ q,
                                                   const float* __restrict__ k,
                                                   const float* __restrict__ v,
                                                   const float* __restrict__ sf) {
    int i = blockIdx.x * 256 + threadIdx.x;
    float4 x;
    uint2 *dh, *dl;
    int j;
    if (i < NQ4) {
        x = ((const float4*)q)[i];
        float s = sf[i >> 16];
        x.x *= s; x.y *= s; x.z *= s; x.w *= s;
        dh = (uint2*)g_QH; dl = (uint2*)g_QL; j = i;
    } else if (i < 2 * NQ4) {
        j = i - NQ4;
        x = ((const float4*)k)[j];
        dh = (uint2*)g_KH; dl = (uint2*)g_KL;
    } else {
        j = i - 2 * NQ4;
        x = ((const float4*)v)[j];
        dh = (uint2*)g_VH; dl = (uint2*)g_VL;
    }
    __half h[4], l[4];
    split2h(x.x, h[0], l[0]); split2h(x.y, h[1], l[1]);
    split2h(x.z, h[2], l[2]); split2h(x.w, h[3], l[3]);
    dh[j] = make_uint2(pack2h(h[0], h[1]), pack2h(h[2], h[3]));
    dl[j] = make_uint2(pack2h(l[0], l[1]), pack2h(l[2], l[3]));
}

// ---------------------------------------------------------------------------
// Main attention kernel
// ---------------------------------------------------------------------------
__global__ void __launch_bounds__(NTHREADS, 1)
attn_fa4_kernel(float* __restrict__ out) {
    extern __shared__ char smem[];
    const uint32_t sb = smem_u32(smem);

    const int b    = blockIdx.y;
    const int q0   = blockIdx.x * MT;
    const int tid  = threadIdx.x;
    const int w    = tid >> 5;
    const int lane = tid & 31;
    const int g    = lane >> 2;
    const int tig  = lane & 3;
    const int m0   = w * 16;
    const int l7   = lane & 7;
    const int b3   = (lane >> 3) & 1;
    const int b4   = lane >> 4;

    const uint32_t aBase   = sb + OFF_QH + (uint32_t)((m0 + l7 + 8 * b3) * ROWB + 16 * b4);
    const uint32_t kLaneOf = (uint32_t)((l7 + 8 * b4) * ROWB + 16 * b3);
    const uint32_t vLaneOf = (uint32_t)((l7 + 8 * b3) * ROWB + 16 * b4);

    // ---- stage Q planes (pure LDG.128 -> STS.128) ----
    {
        const int qrow0 = (b * SQ_ + q0) * 16;
#pragma unroll
        for (int c = 0; c < 8; c++) {
            int f = tid + 256 * c;
            int rr = f >> 4, c4 = f & 15;
            *(uint4*)(smem + OFF_QH + rr * ROWB + c4 * 16) = g_QH[qrow0 + rr * 16 + c4];
            *(uint4*)(smem + OFF_QL + rr * ROWB + c4 * 16) = g_QL[qrow0 + rr * 16 + c4];
        }
    }

    float O[16][4];
#pragma unroll
    for (int nt = 0; nt < 16; nt++) { O[nt][0] = O[nt][1] = O[nt][2] = O[nt][3] = 0.0f; }
    float mr0 = -3.402823466e38f, mr1 = -3.402823466e38f, lr0 = 0.0f, lr1 = 0.0f;

    const uint32_t rowbase = (uint32_t)(b * SQ_ + q0 + m0);
    const int bkb = b * SKV_;

    // prologue: stage tile 0 into buf0
    {
        const uint4* gp[4] = {g_KH, g_KL, g_VH, g_VL};
#pragma unroll
        for (int s = 0; s < 4; s++)
#pragma unroll
            for (int c = 0; c < 4; c++) {
                int f = tid + 256 * c;
                int rr = f >> 4, c4 = f & 15;
                cpasync16(sb + OFF_BUF0 + (uint32_t)(s * 17408 + rr * ROWB + c4 * 16),
                          &gp[s][(bkb + rr) * 16 + c4]);
            }
        CP_COMMIT();
    }

    for (int t = 0; t < NTILES; t++) {
        const int kv0 = t * NT;
        __syncthreads();

        if (t + 1 < NTILES) {
            const uint32_t nbuf = sb + (((t + 1) & 1) ? OFF_BUF1 : OFF_BUF0);
            const int bk = bkb + (t + 1) * NT;
            const uint4* gp[4] = {g_KH, g_KL, g_VH, g_VL};
#pragma unroll
            for (int s = 0; s < 4; s++)
#pragma unroll
                for (int c = 0; c < 4; c++) {
                    int f = tid + 256 * c;
                    int rr = f >> 4, c4 = f & 15;
                    cpasync16(nbuf + (uint32_t)(s * 17408 + rr * ROWB + c4 * 16),
                              &gp[s][(bk + rr) * 16 + c4]);
                }
            CP_COMMIT();
            CP_WAIT1();
        } else {
            CP_WAIT0();
        }
        __syncthreads();

        const uint32_t bufb  = sb + ((t & 1) ? OFF_BUF1 : OFF_BUF0);
        const uint32_t kBase = bufb + BUF_KH + kLaneOf;
        const uint32_t vBase = bufb + BUF_VH + vLaneOf;

        // ---- QK MMAs (3 fp16 passes: HH, HL, LH) + threefry interleaved ----
        float sacc[8][4];
#pragma unroll
        for (int nt = 0; nt < 8; nt++) { sacc[nt][0] = sacc[nt][1] = sacc[nt][2] = sacc[nt][3] = 0.0f; }

        uint32_t kmask = 0;
        const uint32_t idx00 = (rowbase + (uint32_t)g) * (uint32_t)SKV_
                             + (uint32_t)(kv0 + 2 * tig);

#pragma unroll
        for (int k8 = 0; k8 < 8; k8++) {
            {   // dropout mask for n-tile k8 (ALU, overlaps HMMA)
                uint32_t ia = idx00 + (uint32_t)(8 * k8);
                uint32_t ib = ia + 8u * (uint32_t)SKV_;
                uint32_t q0b = (tf_bits(ia)      < KEEP_THRESH) ? 1u : 0u;
                uint32_t q1b = (tf_bits(ia + 1u) < KEEP_THRESH) ? 2u : 0u;
                uint32_t q2b = (tf_bits(ib)      < KEEP_THRESH) ? 4u : 0u;
                uint32_t q3b = (tf_bits(ib + 1u) < KEEP_THRESH) ? 8u : 0u;
                kmask |= (q0b | q1b | q2b | q3b) << (4 * k8);
            }
            uint32_t aH[4], aL[4];
            const uint32_t aAddr = aBase + (uint32_t)(k8 * 32);
            ldsm4(aH, aAddr);
            ldsm4(aL, aAddr + 34816u);
#pragma unroll
            for (int ntp = 0; ntp < 4; ntp++) {
                const uint32_t kAddr = kBase + (uint32_t)(ntp * 16 * ROWB + k8 * 32);
                uint32_t kH[4], kL[4];
                ldsm4(kH, kAddr);
                ldsm4(kL, kAddr + 17408u);
                mma_h(sacc[2 * ntp], aH, kH);
                mma_h(sacc[2 * ntp], aH, kL);
                mma_h(sacc[2 * ntp], aL, kH);
                mma_h(sacc[2 * ntp + 1], aH, kH + 2);
                mma_h(sacc[2 * ntp + 1], aH, kL + 2);
                mma_h(sacc[2 * ntp + 1], aL, kH + 2);
            }
        }

        // ---- softmax + dropout (mask precomputed), intra-warp ----
        float mx0 = sacc[0][0], mx1 = sacc[0][2];
#pragma unroll
        for (int nt = 0; nt < 8; nt++) {
            mx0 = fmaxf(mx0, fmaxf(sacc[nt][0], sacc[nt][1]));
            mx1 = fmaxf(mx1, fmaxf(sacc[nt][2], sacc[nt][3]));
        }
        mx0 = fmaxf(mx0, __shfl_xor_sync(0xffffffffu, mx0, 1));
        mx0 = fmaxf(mx0, __shfl_xor_sync(0xffffffffu, mx0, 2));
        mx1 = fmaxf(mx1, __shfl_xor_sync(0xffffffffu, mx1, 1));
        mx1 = fmaxf(mx1, __shfl_xor_sync(0xffffffffu, mx1, 2));
        float mn0 = fmaxf(mr0, mx0), mn1 = fmaxf(mr1, mx1);
        float al0 = exp2f((mr0 - mn0) * LOG2E_F);
        float al1 = exp2f((mr1 - mn1) * LOG2E_F);

        uint32_t pHa[8], pHb[8];
        float ls0 = 0.0f, ls1 = 0.0f;
#pragma unroll
        for (int nt = 0; nt < 8; nt++) {
            float p0 = exp2f((sacc[nt][0] - mn0) * LOG2E_F);
            float p1 = exp2f((sacc[nt][1] - mn0) * LOG2E_F);
            float p2 = exp2f((sacc[nt][2] - mn1) * LOG2E_F);
            float p3 = exp2f((sacc[nt][3] - mn1) * LOG2E_F);
            ls0 += p0 + p1; ls1 += p2 + p3;
            uint32_t mb = kmask >> (4 * nt);
            float d0 = (mb & 1u) ? p0 * INV_KEEP : 0.0f;
            float d1 = (mb & 2u) ? p1 * INV_KEEP : 0.0f;
            float d2 = (mb & 4u) ? p2 * INV_KEEP : 0.0f;
            float d3 = (mb & 8u) ? p3 * INV_KEEP : 0.0f;
            pHa[nt] = packh2(d0, d1);
            pHb[nt] = packh2(d2, d3);
        }
        ls0 += __shfl_xor_sync(0xffffffffu, ls0, 1);
        ls0 += __shfl_xor_sync(0xffffffffu, ls0, 2);
        ls1 += __shfl_xor_sync(0xffffffffu, ls1, 1);
        ls1 += __shfl_xor_sync(0xffffffffu, ls1, 2);
        lr0 = lr0 * al0 + ls0;
        lr1 = lr1 * al1 + ls1;
        mr0 = mn0; mr1 = mn1;

#pragma unroll
        for (int nt = 0; nt < 16; nt++) {
            O[nt][0] *= al0; O[nt][1] *= al0;
            O[nt][2] *= al1; O[nt][3] *= al1;
        }

        // ---- PV: O += P * V (2 passes: pH·vH + pH·vL; V via ldmatrix.trans) ----
#pragma unroll
        for (int kkp = 0; kkp < 4; kkp++) {
            uint32_t aH[4] = { pHa[2 * kkp], pHb[2 * kkp], pHa[2 * kkp + 1], pHb[2 * kkp + 1] };
#pragma unroll
            for (int ntp = 0; ntp < 8; ntp++) {
                const uint32_t vAddr = vBase + (uint32_t)(kkp * 16 * ROWB + ntp * 32);
                uint32_t vH[4], vL[4];
                ldsm4t(vH, vAddr);
                ldsm4t(vL, vAddr + 17408u);
                mma_h(O[2 * ntp], aH, vH);
                mma_h(O[2 * ntp], aH, vL);
                mma_h(O[2 * ntp + 1], aH, vH + 2);
                mma_h(O[2 * ntp + 1], aH, vL + 2);
            }
        }
    }

    // ---- final: O / l -> gmem ----
    {
        float inv0 = 1.0f / lr0, inv1 = 1.0f / lr1;
        long row0 = (long)(b * SQ_ + q0 + m0 + g);
        float* o0 = out + row0 * D_ + 2 * tig;
        float* o1 = out + (row0 + 8) * D_ + 2 * tig;
#pragma unroll
        for (int nt = 0; nt < 16; nt++) {
            *(float2*)(o0 + 8 * nt) = make_float2(O[nt][0] * inv0, O[nt][1] * inv0);
            *(float2*)(o1 + 8 * nt) = make_float2(O[nt][2] * inv1, O[nt][3] * inv1);
        }
    }
}

// ---------------------------------------------------------------------------
extern "C" void kernel_launch(void* const* d_in, const int* in_sizes, int n_in,
                              void* d_out, int out_size) {
    const float* q  = (const float*)d_in[0];
    const float* k  = (const float*)d_in[1];
    const float* v  = (const float*)d_in[2];
    const float* sf = (const float*)d_in[3];
    float* out = (float*)d_out;

    prep_kernel<<<3 * NQ4 / 256, 256>>>(q, k, v, sf);

    cudaFuncSetAttribute(attn_fa4_kernel,
                         cudaFuncAttributeMaxDynamicSharedMemorySize, SMEM_TOTAL);
    dim3 grid(SQ_ / MT, B_);
    attn_fa4_kernel<<<grid, NTHREADS, SMEM_TOTAL>>>(out);
}